// round 13
// baseline (speedup 1.0000x reference)
#include <cuda_runtime.h>
#include <cuda.h>
#include <cuda_fp16.h>
#include <cstdint>

// Problem constants
#define BB 2
#define TT 2048
#define HH 16
#define DD 64
#define CC 1024
#define MM (BB*TT)        // 4096 rows
#define NQKV (3*CC)       // 3072

// Scratch (device globals -- no allocation allowed)
__device__ __half g_qkvh[MM * NQKV];       // [4096, 3072] fp16 qkv
__device__ __half g_xh[MM * CC];           // x in fp16
__device__ __half g_wqkvh[NQKV * CC];      // w_qkv in fp16
__device__ __half g_wouth[CC * CC];        // w_out in fp16
__device__ __half g_qh[BB*HH*TT*DD];       // [bh][t][d] fp16 (pre-scaled by scale*log2e)
__device__ __half g_kh[BB*HH*TT*DD];       // [bh][t][d] fp16
__device__ __half g_vh[BB*HH*DD*TT];       // [bh][d][t] fp16 (d-major)
__device__ __half g_atth[MM * CC];         // attention out, fp16 [B,T,C]

__device__ __forceinline__ void mma_f16(float* d, const uint32_t* a, const uint32_t* b) {
    asm volatile(
        "mma.sync.aligned.m16n8k16.row.col.f32.f16.f16.f32 "
        "{%0,%1,%2,%3},{%4,%5,%6,%7},{%8,%9},{%0,%1,%2,%3};\n"
        : "+f"(d[0]), "+f"(d[1]), "+f"(d[2]), "+f"(d[3])
        : "r"(a[0]), "r"(a[1]), "r"(a[2]), "r"(a[3]), "r"(b[0]), "r"(b[1]));
}

__device__ __forceinline__ void ldsm4(uint32_t* r, uint32_t addr) {
    asm volatile("ldmatrix.sync.aligned.m8n8.x4.shared.b16 {%0,%1,%2,%3}, [%4];"
                 : "=r"(r[0]), "=r"(r[1]), "=r"(r[2]), "=r"(r[3]) : "r"(addr));
}

__device__ __forceinline__ float ex2(float x) {
    float y;
    asm("ex2.approx.ftz.f32 %0, %1;" : "=f"(y) : "f"(x));
    return y;
}
__device__ __forceinline__ uint32_t ex2h2(uint32_t x) {
    uint32_t y;
    asm("ex2.approx.f16x2 %0, %1;" : "=r"(y) : "r"(x));
    return y;
}

__device__ __forceinline__ void mbar_init(uint32_t addr, uint32_t cnt) {
    asm volatile("mbarrier.init.shared.b64 [%0], %1;" :: "r"(addr), "r"(cnt) : "memory");
}
__device__ __forceinline__ void mbar_expect_tx(uint32_t addr, uint32_t bytes) {
    asm volatile("mbarrier.arrive.expect_tx.shared.b64 _, [%0], %1;"
                 :: "r"(addr), "r"(bytes) : "memory");
}
__device__ __forceinline__ void mbar_wait(uint32_t addr, uint32_t parity) {
    asm volatile(
        "{\n\t.reg .pred P;\n"
        "W:\n\tmbarrier.try_wait.parity.acquire.cta.shared::cta.b64 P, [%0], %1, 0x989680;\n"
        "\t@P bra D;\n\tbra W;\nD:\n\t}"
        :: "r"(addr), "r"(parity) : "memory");
}
__device__ __forceinline__ void tma2d(uint32_t smem, const CUtensorMap* map,
                                      int x, int y, uint32_t bar) {
    asm volatile(
        "cp.async.bulk.tensor.2d.shared::cta.global.tile.mbarrier::complete_tx::bytes "
        "[%0], [%1, {%2, %3}], [%4];"
        :: "r"(smem), "l"(map), "r"(x), "r"(y), "r"(bar) : "memory");
}
__device__ __forceinline__ void tma3d(uint32_t smem, const CUtensorMap* map,
                                      int x, int y, int z, uint32_t bar) {
    asm volatile(
        "cp.async.bulk.tensor.3d.shared::cta.global.tile.mbarrier::complete_tx::bytes "
        "[%0], [%1, {%2, %3, %4}], [%5];"
        :: "r"(smem), "l"(map), "r"(x), "r"(y), "r"(z), "r"(bar) : "memory");
}

// ---------------------------------------------------------------------------
// fp32 -> fp16 convert (vectorized, 8 elems/thread)
// ---------------------------------------------------------------------------
__global__ __launch_bounds__(256) void cvt_h(
    const float* __restrict__ src, __half* __restrict__ dst, int n)
{
    int i = (blockIdx.x * blockDim.x + threadIdx.x) * 8;
    if (i >= n) return;
    float4 v0 = *(const float4*)(src + i);
    float4 v1 = *(const float4*)(src + i + 4);
    __half2 h0 = __floats2half2_rn(v0.x, v0.y);
    __half2 h1 = __floats2half2_rn(v0.z, v0.w);
    __half2 h2 = __floats2half2_rn(v1.x, v1.y);
    __half2 h3 = __floats2half2_rn(v1.z, v1.w);
    uint4 o;
    o.x = *(uint32_t*)&h0; o.y = *(uint32_t*)&h1;
    o.z = *(uint32_t*)&h2; o.w = *(uint32_t*)&h3;
    *(uint4*)(dst + i) = o;
}

// ---------------------------------------------------------------------------
// TMA fp16 GEMM (unchanged from R12 pass): C[m][n] = sum_k A[m][k]*B[n][k]
// ---------------------------------------------------------------------------
#define GS 3
#define GA_B 16384
#define GSTG (2*GA_B)                       // 32768 per stage (A+B)
#define GEMM_SMEM (1024 + GS*GSTG)          // 99328

template <typename OutT>
__global__ __launch_bounds__(256, 2) void gemm_tma(
    const __grid_constant__ CUtensorMap mA,
    const __grid_constant__ CUtensorMap mB,
    OutT* __restrict__ C, int N, int K)
{
    extern __shared__ __align__(128) char smc[];
    uint32_t sb = (uint32_t)__cvta_generic_to_shared(smc);
    const uint32_t mbar = sb;
    const uint32_t tiles = sb + 1024;

    const int tid  = threadIdx.x;
    const int lane = tid & 31;
    const int warp = tid >> 5;
    const int wm = warp & 1;
    const int wn = warp >> 1;
    const int m0 = blockIdx.y * 128;
    const int n0 = blockIdx.x * 128;
    const int g  = lane >> 3;
    const int lr = lane & 7;
    const int gm = lane >> 2;
    const int gk = lane & 3;

    const int NI = K / 64;

    if (tid == 0) {
        #pragma unroll
        for (int s = 0; s < GS; s++) mbar_init(mbar + 8 * s, 1);
    }
    __syncthreads();

    auto prod = [&](int kt, int s) {
        uint32_t bar = mbar + 8 * s;
        mbar_expect_tx(bar, GSTG);
        tma2d(tiles + s * GSTG,        &mA, kt * 64, m0, bar);
        tma2d(tiles + s * GSTG + GA_B, &mB, kt * 64, n0, bar);
    };
    if (tid == 0) { prod(0, 0); prod(1, 1); prod(2, 2); }

    uint32_t arow[4], brow[2];
    #pragma unroll
    for (int i = 0; i < 4; i++)
        arow[i] = (uint32_t)((wm * 64 + 16 * i + (g & 1) * 8 + lr) * 128);
    #pragma unroll
    for (int jj = 0; jj < 2; jj++)
        brow[jj] = (uint32_t)(GA_B + (wn * 32 + 16 * jj + (g >> 1) * 8 + lr) * 128);

    float acc[16][4];
    #pragma unroll
    for (int t = 0; t < 16; t++)
        #pragma unroll
        for (int r = 0; r < 4; r++) acc[t][r] = 0.f;

    for (int it = 0; it < NI; it++) {
        const int s = it % GS;
        const uint32_t ph = (uint32_t)((it / GS) & 1);
        mbar_wait(mbar + 8 * s, ph);

        const uint32_t stg = tiles + s * GSTG;
        #pragma unroll
        for (int ks = 0; ks < 4; ks++) {
            uint32_t af[4][4];
            const uint32_t ag = (uint32_t)(((2 * ks + (g >> 1)) ^ lr) << 4);
            #pragma unroll
            for (int i = 0; i < 4; i++)
                ldsm4(af[i], stg + arow[i] + ag);
            uint32_t bf[2][4];
            const uint32_t bg = (uint32_t)(((2 * ks + (g & 1)) ^ lr) << 4);
            #pragma unroll
            for (int jj = 0; jj < 2; jj++)
                ldsm4(bf[jj], stg + brow[jj] + bg);

            #pragma unroll
            for (int i = 0; i < 4; i++)
                #pragma unroll
                for (int jj = 0; jj < 2; jj++) {
                    mma_f16(acc[i * 4 + 2 * jj],     af[i], &bf[jj][0]);
                    mma_f16(acc[i * 4 + 2 * jj + 1], af[i], &bf[jj][2]);
                }
        }
        __syncthreads();
        if (tid == 0 && it + GS < NI) prod(it + GS, s);
    }

    #pragma unroll
    for (int i = 0; i < 4; i++) {
        #pragma unroll
        for (int nn = 0; nn < 4; nn++) {
            float* a = acc[i * 4 + nn];
            int r = m0 + wm * 64 + 16 * i + gm;
            int c = n0 + wn * 32 + 8 * nn + (gk << 1);
            if constexpr (sizeof(OutT) == 4) {
                float2 v0 = {a[0], a[1]};
                float2 v1 = {a[2], a[3]};
                *(float2*)((float*)C + (size_t)r * N + c) = v0;
                *(float2*)((float*)C + (size_t)(r + 8) * N + c) = v1;
            } else {
                __half2 v0 = __floats2half2_rn(a[0], a[1]);
                __half2 v1 = __floats2half2_rn(a[2], a[3]);
                *(uint32_t*)((__half*)C + (size_t)r * N + c) = *(uint32_t*)&v0;
                *(uint32_t*)((__half*)C + (size_t)(r + 8) * N + c) = *(uint32_t*)&v1;
            }
        }
    }
}

// ---------------------------------------------------------------------------
// RoPE + scatter q,k (fp16 qkv in) -> fp16 [bh][t][d].
// q pre-scaled by scale*log2e so attention scores land in log2 domain.
// ---------------------------------------------------------------------------
#define QSCALE 0.1803368801f   // 0.125 * log2(e)

__global__ __launch_bounds__(256) void rope_scatter(
    const float* __restrict__ cosp, const float* __restrict__ sinp)
{
    int idx = blockIdx.x * blockDim.x + threadIdx.x;
    if (idx >= BB * TT * HH * 32) return;
    int d = idx & 31;
    int h = (idx >> 5) & (HH - 1);
    int t = (idx >> 9) & (TT - 1);
    int b = idx >> 20;

    const __half* row = g_qkvh + (size_t)(b * TT + t) * NQKV;
    int base = h * DD + d;

    float c0 = cosp[t * DD + d],      c1 = cosp[t * DD + d + 32];
    float s0 = sinp[t * DD + d],      s1 = sinp[t * DD + d + 32];

    float q0 = __half2float(row[base]),      q1 = __half2float(row[base + 32]);
    float k0 = __half2float(row[CC + base]), k1 = __half2float(row[CC + base + 32]);

    size_t hoff = ((size_t)(b * HH + h) * TT + t) * DD + d;
    g_qh[hoff]      = __float2half((q0 * c0 - q1 * s0) * QSCALE);
    g_qh[hoff + 32] = __float2half((q1 * c1 + q0 * s1) * QSCALE);
    g_kh[hoff]      = __float2half(k0 * c0 - k1 * s0);
    g_kh[hoff + 32] = __float2half(k1 * c1 + k0 * s1);
}

// ---------------------------------------------------------------------------
// V transpose: fp16 qkv v-part [b,t,h*64+d] -> g_vh [bh][d][t].
// ---------------------------------------------------------------------------
__global__ __launch_bounds__(256) void v_transpose()
{
    __shared__ __half s[64][40];

    const int bh = blockIdx.y;
    const int b = bh >> 4, h = bh & 15;
    const int t0 = blockIdx.x * 32;
    const int tid = threadIdx.x;

    {
        int t = tid >> 3;
        int d8 = (tid & 7) << 3;
        const __half* src = g_qkvh + (size_t)(b * TT + t0 + t) * NQKV + 2 * CC + h * DD + d8;
        uint4 v = *(const uint4*)src;
        __half hv[8];
        *(uint4*)hv = v;
        #pragma unroll
        for (int i = 0; i < 8; i++) s[d8 + i][t] = hv[i];
    }
    __syncthreads();

    {
        int d = tid >> 2;
        int tq = (tid & 3) << 3;
        uint4 v = *(const uint4*)&s[d][tq];
        __half* dst = g_vh + ((size_t)bh * DD + d) * TT + t0 + tq;
        *(uint4*)dst = v;
    }
}

// ---------------------------------------------------------------------------
// TMA fp16 causal flash attention.
// - B-frags via ldmatrix.x4 (R12).
// - exp via ex2.approx.f16x2 (halves MUFU ops, results already packed fp16).
// - l via ones-column: V tile has 80 rows; row 64 = 1.0 (swizzle key 0 ->
//   linear write valid), rows 65-79 = 0. PV's 9th accumulator's col0 = l.
// K tile: [64 keys][128B], V tile: [80 d-rows][128B], SW128.
// ---------------------------------------------------------------------------
#define AKT_B 8192
#define AVT_B (80*128)                      // 10240
#define ASTG (AKT_B+AVT_B)                  // 18432
#define AST 3
#define ATTN_SMEM (1024 + AST*ASTG)         // 56320

__global__ __launch_bounds__(256, 2) void attn_tma(
    const __grid_constant__ CUtensorMap mK,
    const __grid_constant__ CUtensorMap mV)
{
    const int bh = blockIdx.y;
    const int q0 = (gridDim.x - 1 - blockIdx.x) * 128;
    const int b = bh >> 4, h = bh & 15;
    const int tid = threadIdx.x;
    const int lane = tid & 31;
    const int w = tid >> 5;
    const int gm = lane >> 2;
    const int gk = lane & 3;
    const int g  = lane >> 3;
    const int lr = lane & 7;

    const __half* Qp = g_qh + (size_t)bh * TT * DD;

    extern __shared__ __align__(128) char smc[];
    uint32_t sb = (uint32_t)__cvta_generic_to_shared(smc);
    const uint32_t mbar = sb;

    const int rowA = q0 + w * 16 + gm;
    const int wrow_lo = q0 + w * 16;
    const int wrow_hi = wrow_lo + 15;

    const int ntiles = (q0 + 128) / 64;

    if (tid == 0) {
        #pragma unroll
        for (int s = 0; s < AST; s++) mbar_init(mbar + 8 * s, 1);
    }
    // ones/zero rows 64..79 of each V stage buffer (TMA never touches them)
    #pragma unroll
    for (int s = 0; s < AST; s++) {
        __half* vrows = (__half*)(smc + 1024 + s * ASTG + AKT_B + 64 * 128);
        for (int i = tid; i < 16 * 64; i += 256)
            vrows[i] = (i < 64) ? __float2half(1.f) : __float2half(0.f);
    }
    __syncthreads();

    const uint32_t tiles_u32 = sb + 1024;
    auto prod = [&](int jt, int s) {
        uint32_t bar = mbar + 8 * s;
        mbar_expect_tx(bar, AKT_B + 64 * 128);
        tma3d(tiles_u32 + s * ASTG,         &mK, 0, jt * 64, bh, bar);
        tma3d(tiles_u32 + s * ASTG + AKT_B, &mV, jt * 64, 0, bh, bar);
    };
    if (tid == 0) {
        prod(0, 0);
        prod(1, 1);
        if (ntiles > 2) prod(2, 2);
    }

    uint32_t qf[4][4];
    #pragma unroll
    for (int s = 0; s < 4; s++) {
        const __half* r0 = Qp + (size_t)rowA * DD + 16 * s + 2 * gk;
        const __half* r1 = Qp + (size_t)(rowA + 8) * DD + 16 * s + 2 * gk;
        qf[s][0] = *(const uint32_t*)r0;
        qf[s][1] = *(const uint32_t*)r1;
        qf[s][2] = *(const uint32_t*)(r0 + 8);
        qf[s][3] = *(const uint32_t*)(r1 + 8);
    }

    const uint32_t lrowoff = (uint32_t)(((g >> 1) * 8 + lr) * 128);

    float o[9][4];                      // o[8] = l accumulator (ones column)
    #pragma unroll
    for (int n = 0; n < 9; n++)
        #pragma unroll
        for (int r = 0; r < 4; r++) o[n][r] = 0.f;
    float mA = -1e30f, mB = -1e30f;

    for (int jt = 0; jt < ntiles; jt++) {
        const int st = jt % AST;
        mbar_wait(mbar + 8 * st, (uint32_t)((jt / AST) & 1));

        const uint32_t Ks = tiles_u32 + st * ASTG;
        const uint32_t Vs = Ks + AKT_B;
        const int j0 = jt * 64;

        if (j0 <= wrow_hi) {
            // ---- S = Q K^T (16 x 64): ldmatrix.x4 B-frags; log2 domain ----
            float sf[8][4];
            #pragma unroll
            for (int j = 0; j < 8; j++)
                #pragma unroll
                for (int r = 0; r < 4; r++) sf[j][r] = 0.f;
            #pragma unroll
            for (int s = 0; s < 4; s++) {
                const uint32_t bg = (uint32_t)(((2 * s + (g & 1)) ^ lr) << 4);
                #pragma unroll
                for (int jp = 0; jp < 4; jp++) {
                    uint32_t bf[4];
                    ldsm4(bf, Ks + (uint32_t)(16 * jp * 128) + lrowoff + bg);
                    mma_f16(sf[2 * jp],     qf[s], &bf[0]);
                    mma_f16(sf[2 * jp + 1], qf[s], &bf[2]);
                }
            }

            // ---- mask + row max (scale already folded into Q) ----
            const bool needmask = (j0 + 63 > wrow_lo);
            float mxA = -1e30f, mxB = -1e30f;
            #pragma unroll
            for (int j = 0; j < 8; j++) {
                #pragma unroll
                for (int e = 0; e < 2; e++) {
                    int col = j0 + 8 * j + 2 * gk + e;
                    float v0 = sf[j][e];
                    float v1 = sf[j][2 + e];
                    if (needmask) {
                        if (col > rowA)     v0 = -1e30f;
                        if (col > rowA + 8) v1 = -1e30f;
                    }
                    sf[j][e] = v0; sf[j][2 + e] = v1;
                    mxA = fmaxf(mxA, v0); mxB = fmaxf(mxB, v1);
                }
            }
            mxA = fmaxf(mxA, __shfl_xor_sync(0xffffffffu, mxA, 1));
            mxA = fmaxf(mxA, __shfl_xor_sync(0xffffffffu, mxA, 2));
            mxB = fmaxf(mxB, __shfl_xor_sync(0xffffffffu, mxB, 1));
            mxB = fmaxf(mxB, __shfl_xor_sync(0xffffffffu, mxB, 2));

            float nmA = fmaxf(mA, mxA), nmB = fmaxf(mB, mxB);
            float aA = ex2(mA - nmA), aB = ex2(mB - nmB);
            mA = nmA; mB = nmB;

            #pragma unroll
            for (int n = 0; n < 9; n++) {
                o[n][0] *= aA; o[n][1] *= aA;
                o[n][2] *= aB; o[n][3] *= aB;
            }

            // ---- P = exp2(S - m) in fp16x2 (already packed A-frags) ----
            uint32_t phl[8][2];
            #pragma unroll
            for (int j = 0; j < 8; j++) {
                __half2 h01 = __floats2half2_rn(sf[j][0] - mA, sf[j][1] - mA);
                __half2 h23 = __floats2half2_rn(sf[j][2] - mB, sf[j][3] - mB);
                phl[j][0] = ex2h2(*(const uint32_t*)&h01);
                phl[j][1] = ex2h2(*(const uint32_t*)&h23);
            }

            // ---- O += P V (+ l via ones row 64) ----
            #pragma unroll
            for (int s2 = 0; s2 < 4; s2++) {
                uint32_t af[4] = { phl[2 * s2][0], phl[2 * s2][1],
                                   phl[2 * s2 + 1][0], phl[2 * s2 + 1][1] };
                const uint32_t vg = (uint32_t)(((2 * s2 + (g & 1)) ^ lr) << 4);
                #pragma unroll
                for (int jp = 0; jp < 4; jp++) {
                    uint32_t bf[4];
                    ldsm4(bf, Vs + (uint32_t)(16 * jp * 128) + lrowoff + vg);
                    mma_f16(o[2 * jp],     af, &bf[0]);
                    mma_f16(o[2 * jp + 1], af, &bf[2]);
                }
                uint32_t bfl[4];
                ldsm4(bfl, Vs + (uint32_t)(64 * 128) + lrowoff + vg);
                mma_f16(o[8], af, &bfl[0]);
            }
        }
        __syncthreads();
        if (tid == 0 && jt + AST < ntiles) prod(jt + AST, st);
    }

    // l lives in o[8] col 0 (= quad lane gk=0, element 0)
    const int src0 = lane & ~3;
    float lA = __shfl_sync(0xffffffffu, o[8][0], src0);
    float lB = __shfl_sync(0xffffffffu, o[8][2], src0);
    float invA = 1.f / lA, invB = 1.f / lB;

    __half* dstA = g_atth + (size_t)(b * TT + rowA) * CC + h * DD;
    __half* dstB = g_atth + (size_t)(b * TT + rowA + 8) * CC + h * DD;
    #pragma unroll
    for (int n = 0; n < 8; n++) {
        int cix = 8 * n + 2 * gk;
        __half2 v0 = __floats2half2_rn(o[n][0] * invA, o[n][1] * invA);
        __half2 v1 = __floats2half2_rn(o[n][2] * invB, o[n][3] * invB);
        *(uint32_t*)(dstA + cix) = *(uint32_t*)&v0;
        *(uint32_t*)(dstB + cix) = *(uint32_t*)&v1;
    }
}

// ---------------------------------------------------------------------------
// Host: tensor-map encode via driver entry point
// ---------------------------------------------------------------------------
typedef CUresult (*PFN_tmap_encode)(
    CUtensorMap*, CUtensorMapDataType, cuuint32_t, void*,
    const cuuint64_t*, const cuuint64_t*, const cuuint32_t*, const cuuint32_t*,
    CUtensorMapInterleave, CUtensorMapSwizzle, CUtensorMapL2promotion,
    CUtensorMapFloatOOBfill);

static PFN_tmap_encode get_encoder() {
    void* fn = nullptr;
    cudaDriverEntryPointQueryResult qr;
    cudaGetDriverEntryPoint("cuTensorMapEncodeTiled", &fn, cudaEnableDefault, &qr);
    return (PFN_tmap_encode)fn;
}

static void enc2d(PFN_tmap_encode f, CUtensorMap* m, void* base,
                  uint64_t d0, uint64_t d1, uint32_t b0, uint32_t b1) {
    cuuint64_t dims[2] = {d0, d1};
    cuuint64_t str[1]  = {d0 * 2};
    cuuint32_t box[2]  = {b0, b1};
    cuuint32_t es[2]   = {1, 1};
    f(m, CU_TENSOR_MAP_DATA_TYPE_FLOAT16, 2, base, dims, str, box, es,
      CU_TENSOR_MAP_INTERLEAVE_NONE, CU_TENSOR_MAP_SWIZZLE_128B,
      CU_TENSOR_MAP_L2_PROMOTION_L2_128B, CU_TENSOR_MAP_FLOAT_OOB_FILL_NONE);
}

static void enc3d(PFN_tmap_encode f, CUtensorMap* m, void* base,
                  uint64_t d0, uint64_t d1, uint64_t d2,
                  uint32_t b0, uint32_t b1) {
    cuuint64_t dims[3] = {d0, d1, d2};
    cuuint64_t str[2]  = {d0 * 2, d0 * d1 * 2};
    cuuint32_t box[3]  = {b0, b1, 1};
    cuuint32_t es[3]   = {1, 1, 1};
    f(m, CU_TENSOR_MAP_DATA_TYPE_FLOAT16, 3, base, dims, str, box, es,
      CU_TENSOR_MAP_INTERLEAVE_NONE, CU_TENSOR_MAP_SWIZZLE_128B,
      CU_TENSOR_MAP_L2_PROMOTION_L2_128B, CU_TENSOR_MAP_FLOAT_OOB_FILL_NONE);
}

// ---------------------------------------------------------------------------
// Launch
// ---------------------------------------------------------------------------
extern "C" void kernel_launch(void* const* d_in, const int* in_sizes, int n_in,
                              void* d_out, int out_size)
{
    const float* x     = (const float*)d_in[0];
    const float* cosp  = (const float*)d_in[1];
    const float* sinp  = (const float*)d_in[2];
    const float* w_qkv = (const float*)d_in[3];
    const float* w_out = (const float*)d_in[4];
    float* out = (float*)d_out;

    __half *p_qkvh, *p_xh, *p_wqkvh, *p_wouth, *p_kh, *p_vh, *p_atth;
    cudaGetSymbolAddress((void**)&p_qkvh,  g_qkvh);
    cudaGetSymbolAddress((void**)&p_xh,    g_xh);
    cudaGetSymbolAddress((void**)&p_wqkvh, g_wqkvh);
    cudaGetSymbolAddress((void**)&p_wouth, g_wouth);
    cudaGetSymbolAddress((void**)&p_kh,    g_kh);
    cudaGetSymbolAddress((void**)&p_vh,    g_vh);
    cudaGetSymbolAddress((void**)&p_atth,  g_atth);

    PFN_tmap_encode enc = get_encoder();

    CUtensorMap mX, mWqkv, mAtt, mWout, mK, mV;
    enc2d(enc, &mX,    p_xh,    CC, MM,   64, 128);
    enc2d(enc, &mWqkv, p_wqkvh, CC, NQKV, 64, 128);
    enc2d(enc, &mAtt,  p_atth,  CC, MM,   64, 128);
    enc2d(enc, &mWout, p_wouth, CC, CC,   64, 128);
    enc3d(enc, &mK, p_kh, DD, TT, BB * HH, 64, 64);
    enc3d(enc, &mV, p_vh, TT, DD, BB * HH, 64, 64);

    cudaFuncSetAttribute(gemm_tma<__half>,
                         cudaFuncAttributeMaxDynamicSharedMemorySize, GEMM_SMEM);
    cudaFuncSetAttribute(gemm_tma<float>,
                         cudaFuncAttributeMaxDynamicSharedMemorySize, GEMM_SMEM);
    cudaFuncSetAttribute(attn_tma,
                         cudaFuncAttributeMaxDynamicSharedMemorySize, ATTN_SMEM);

    // 0) fp32 -> fp16 converts
    cvt_h<<<(MM * CC) / (8 * 256), 256>>>(x, p_xh, MM * CC);
    cvt_h<<<(NQKV * CC) / (8 * 256), 256>>>(w_qkv, p_wqkvh, NQKV * CC);
    cvt_h<<<(CC * CC) / (8 * 256), 256>>>(w_out, p_wouth, CC * CC);

    // 1) qkv = x @ w_qkv^T (fp16 out)
    {
        dim3 grid(NQKV / 128, MM / 128);
        gemm_tma<__half><<<grid, 256, GEMM_SMEM>>>(mX, mWqkv, p_qkvh, NQKV, CC);
    }

    // 2a) RoPE q,k -> fp16 [bh][t][d] (q pre-scaled)
    {
        int total = BB * TT * HH * 32;
        rope_scatter<<<(total + 255) / 256, 256>>>(cosp, sinp);
    }
    // 2b) V -> fp16 [bh][d][t]
    {
        dim3 grid(TT / 32, BB * HH);
        v_transpose<<<grid, 256>>>();
    }

    // 3) TMA fp16 causal flash attention
    {
        dim3 grid(TT / 128, BB * HH);
        attn_tma<<<grid, 256, ATTN_SMEM>>>(mK, mV);
    }

    // 4) out = att @ w_out^T (fp32 out)
    {
        dim3 grid(CC / 128, MM / 128);
        gemm_tma<float><<<grid, 256, GEMM_SMEM>>>(mAtt, mWout, out, CC, CC);
    }
}

// round 14
// speedup vs baseline: 1.0652x; 1.0652x over previous
#include <cuda_runtime.h>
#include <cuda.h>
#include <cuda_fp16.h>
#include <cstdint>

// Problem constants
#define BB 2
#define TT 2048
#define HH 16
#define DD 64
#define CC 1024
#define MM (BB*TT)        // 4096 rows
#define NQKV (3*CC)       // 3072

// Scratch (device globals -- no allocation allowed)
__device__ __half g_xh[MM * CC];           // x in fp16
__device__ __half g_wqkvh[NQKV * CC];      // w_qkv in fp16
__device__ __half g_wouth[CC * CC];        // w_out in fp16
__device__ __half g_qh[BB*HH*TT*DD];       // [bh][t][d] fp16 (post-RoPE)
__device__ __half g_kh[BB*HH*TT*DD];       // [bh][t][d] fp16 (post-RoPE)
__device__ __half g_vh[BB*HH*DD*TT];       // [bh][d][t] fp16 (d-major)
__device__ __half g_atth[MM * CC];         // attention out, fp16 [B,T,C]

__device__ __forceinline__ float ex2(float x) {
    float y;
    asm("ex2.approx.ftz.f32 %0, %1;" : "=f"(y) : "f"(x));
    return y;
}

__device__ __forceinline__ void mma_f16(float* d, const uint32_t* a, const uint32_t* b) {
    asm volatile(
        "mma.sync.aligned.m16n8k16.row.col.f32.f16.f16.f32 "
        "{%0,%1,%2,%3},{%4,%5,%6,%7},{%8,%9},{%0,%1,%2,%3};\n"
        : "+f"(d[0]), "+f"(d[1]), "+f"(d[2]), "+f"(d[3])
        : "r"(a[0]), "r"(a[1]), "r"(a[2]), "r"(a[3]), "r"(b[0]), "r"(b[1]));
}

__device__ __forceinline__ void ldsm4(uint32_t* r, uint32_t addr) {
    asm volatile("ldmatrix.sync.aligned.m8n8.x4.shared.b16 {%0,%1,%2,%3}, [%4];"
                 : "=r"(r[0]), "=r"(r[1]), "=r"(r[2]), "=r"(r[3]) : "r"(addr));
}

__device__ __forceinline__ void mbar_init(uint32_t addr, uint32_t cnt) {
    asm volatile("mbarrier.init.shared.b64 [%0], %1;" :: "r"(addr), "r"(cnt) : "memory");
}
__device__ __forceinline__ void mbar_expect_tx(uint32_t addr, uint32_t bytes) {
    asm volatile("mbarrier.arrive.expect_tx.shared.b64 _, [%0], %1;"
                 :: "r"(addr), "r"(bytes) : "memory");
}
__device__ __forceinline__ void mbar_wait(uint32_t addr, uint32_t parity) {
    asm volatile(
        "{\n\t.reg .pred P;\n"
        "W:\n\tmbarrier.try_wait.parity.acquire.cta.shared::cta.b64 P, [%0], %1, 0x989680;\n"
        "\t@P bra D;\n\tbra W;\nD:\n\t}"
        :: "r"(addr), "r"(parity) : "memory");
}
__device__ __forceinline__ void tma2d(uint32_t smem, const CUtensorMap* map,
                                      int x, int y, uint32_t bar) {
    asm volatile(
        "cp.async.bulk.tensor.2d.shared::cta.global.tile.mbarrier::complete_tx::bytes "
        "[%0], [%1, {%2, %3}], [%4];"
        :: "r"(smem), "l"(map), "r"(x), "r"(y), "r"(bar) : "memory");
}
__device__ __forceinline__ void tma3d(uint32_t smem, const CUtensorMap* map,
                                      int x, int y, int z, uint32_t bar) {
    asm volatile(
        "cp.async.bulk.tensor.3d.shared::cta.global.tile.mbarrier::complete_tx::bytes "
        "[%0], [%1, {%2, %3, %4}], [%5];"
        :: "r"(smem), "l"(map), "r"(x), "r"(y), "r"(z), "r"(bar) : "memory");
}

// ---------------------------------------------------------------------------
// fp32 -> fp16 convert (vectorized, 8 elems/thread)
// ---------------------------------------------------------------------------
__global__ __launch_bounds__(256) void cvt_h(
    const float* __restrict__ src, __half* __restrict__ dst, int n)
{
    int i = (blockIdx.x * blockDim.x + threadIdx.x) * 8;
    if (i >= n) return;
    float4 v0 = *(const float4*)(src + i);
    float4 v1 = *(const float4*)(src + i + 4);
    __half2 h0 = __floats2half2_rn(v0.x, v0.y);
    __half2 h1 = __floats2half2_rn(v0.z, v0.w);
    __half2 h2 = __floats2half2_rn(v1.x, v1.y);
    __half2 h3 = __floats2half2_rn(v1.z, v1.w);
    uint4 o;
    o.x = *(uint32_t*)&h0; o.y = *(uint32_t*)&h1;
    o.z = *(uint32_t*)&h2; o.w = *(uint32_t*)&h3;
    *(uint4*)(dst + i) = o;
}

// ---------------------------------------------------------------------------
// Shared GEMM pipeline pieces
// ---------------------------------------------------------------------------
#define GS 3
#define GA_B 16384
#define GSTG (2*GA_B)                       // 32768 per stage (A+B)
#define GEMM_SMEM (1024 + GS*GSTG)          // 99328
#define CPITCH 136                          // halves; epilogue smem tile pitch

// ---------------------------------------------------------------------------
// qkv GEMM with fused RoPE + scatter epilogue.
// C tile (128 rows x 128 cols of qkv) -> smem -> directly into
// g_qh/g_kh (RoPE applied) or g_vh (d-major transpose). No qkv intermediate.
// ---------------------------------------------------------------------------
__global__ __launch_bounds__(256, 2) void gemm_qkv(
    const __grid_constant__ CUtensorMap mA,
    const __grid_constant__ CUtensorMap mB,
    const float* __restrict__ cosp, const float* __restrict__ sinp,
    int N, int K)
{
    extern __shared__ __align__(128) char smc[];
    uint32_t sb = (uint32_t)__cvta_generic_to_shared(smc);
    const uint32_t mbar = sb;
    const uint32_t tiles = sb + 1024;

    const int tid  = threadIdx.x;
    const int lane = tid & 31;
    const int warp = tid >> 5;
    const int wm = warp & 1;
    const int wn = warp >> 1;
    const int m0 = blockIdx.y * 128;
    const int n0 = blockIdx.x * 128;
    const int g  = lane >> 3;
    const int lr = lane & 7;
    const int gm = lane >> 2;
    const int gk = lane & 3;

    const int NI = K / 64;

    if (tid == 0) {
        #pragma unroll
        for (int s = 0; s < GS; s++) mbar_init(mbar + 8 * s, 1);
    }
    __syncthreads();

    auto prod = [&](int kt, int s) {
        uint32_t bar = mbar + 8 * s;
        mbar_expect_tx(bar, GSTG);
        tma2d(tiles + s * GSTG,        &mA, kt * 64, m0, bar);
        tma2d(tiles + s * GSTG + GA_B, &mB, kt * 64, n0, bar);
    };
    if (tid == 0) { prod(0, 0); prod(1, 1); prod(2, 2); }

    uint32_t arow[4], brow[2];
    #pragma unroll
    for (int i = 0; i < 4; i++)
        arow[i] = (uint32_t)((wm * 64 + 16 * i + (g & 1) * 8 + lr) * 128);
    #pragma unroll
    for (int jj = 0; jj < 2; jj++)
        brow[jj] = (uint32_t)(GA_B + (wn * 32 + 16 * jj + (g >> 1) * 8 + lr) * 128);

    float acc[16][4];
    #pragma unroll
    for (int t = 0; t < 16; t++)
        #pragma unroll
        for (int r = 0; r < 4; r++) acc[t][r] = 0.f;

    for (int it = 0; it < NI; it++) {
        const int s = it % GS;
        const uint32_t ph = (uint32_t)((it / GS) & 1);
        mbar_wait(mbar + 8 * s, ph);

        const uint32_t stg = tiles + s * GSTG;
        #pragma unroll
        for (int ks = 0; ks < 4; ks++) {
            uint32_t af[4][4];
            const uint32_t ag = (uint32_t)(((2 * ks + (g >> 1)) ^ lr) << 4);
            #pragma unroll
            for (int i = 0; i < 4; i++)
                ldsm4(af[i], stg + arow[i] + ag);
            uint32_t bf[2][4];
            const uint32_t bg = (uint32_t)(((2 * ks + (g & 1)) ^ lr) << 4);
            #pragma unroll
            for (int jj = 0; jj < 2; jj++)
                ldsm4(bf[jj], stg + brow[jj] + bg);

            #pragma unroll
            for (int i = 0; i < 4; i++)
                #pragma unroll
                for (int jj = 0; jj < 2; jj++) {
                    mma_f16(acc[i * 4 + 2 * jj],     af[i], &bf[jj][0]);
                    mma_f16(acc[i * 4 + 2 * jj + 1], af[i], &bf[jj][2]);
                }
        }
        __syncthreads();
        if (tid == 0 && it + GS < NI) prod(it + GS, s);
    }

    // ---- fused epilogue: park C tile in smem (pipeline smem is free) ----
    __half* cs = (__half*)(smc + 1024);
    #pragma unroll
    for (int i = 0; i < 4; i++) {
        #pragma unroll
        for (int nn = 0; nn < 4; nn++) {
            float* a = acc[i * 4 + nn];
            int r  = wm * 64 + 16 * i + gm;
            int cp = wn * 32 + 8 * nn + (gk << 1);
            __half2 v0 = __floats2half2_rn(a[0], a[1]);
            __half2 v1 = __floats2half2_rn(a[2], a[3]);
            *(uint32_t*)(cs + r * CPITCH + cp)       = *(uint32_t*)&v0;
            *(uint32_t*)(cs + (r + 8) * CPITCH + cp) = *(uint32_t*)&v1;
        }
    }
    __syncthreads();

    // ---- scatter: thread = one tile column x 64 rows ----
    const int colg  = tid & 127;           // local col
    const int rhalf = tid >> 7;            // 0/1
    const int c   = n0 + colg;             // global f index 0..3071
    const int reg = c >> 10;               // 0=q 1=k 2=v
    const int hd  = c & 1023;
    const int h   = hd >> 6, d = hd & 63;
    const int mb  = m0 + rhalf * 64;       // first global row
    const int b   = mb >> 11;
    const int lr0 = rhalf * 64;            // first local row

    if (reg < 2) {
        const int pcol = colg ^ 32;        // RoPE partner column (d +/- 32)
        __half* dst = (reg == 0 ? g_qh : g_kh)
                      + ((size_t)(b * HH + h) * TT) * DD + d;
        const float sgn = (d < 32) ? -1.f : 1.f;
        for (int rr = 0; rr < 64; rr++) {
            int t = (mb + rr) & (TT - 1);
            float cv = cosp[t * DD + d];
            float sv = sinp[t * DD + d];
            float xm = __half2float(cs[(lr0 + rr) * CPITCH + colg]);
            float xp = __half2float(cs[(lr0 + rr) * CPITCH + pcol]);
            dst[(size_t)t * DD] = __float2half(xm * cv + sgn * xp * sv);
        }
    } else {
        __half* dst = g_vh + ((size_t)(b * HH + h) * DD + d) * TT;
        for (int rr = 0; rr < 64; rr += 8) {
            __half tmp[8];
            #pragma unroll
            for (int k = 0; k < 8; k++)
                tmp[k] = cs[(lr0 + rr + k) * CPITCH + colg];
            int t = (mb + rr) & (TT - 1);
            *(uint4*)(dst + t) = *(uint4*)tmp;
        }
    }
}

// ---------------------------------------------------------------------------
// Output-projection GEMM (unchanged R12 path): C = A @ B^T, fp32 out.
// ---------------------------------------------------------------------------
__global__ __launch_bounds__(256, 2) void gemm_out(
    const __grid_constant__ CUtensorMap mA,
    const __grid_constant__ CUtensorMap mB,
    float* __restrict__ C, int N, int K)
{
    extern __shared__ __align__(128) char smc[];
    uint32_t sb = (uint32_t)__cvta_generic_to_shared(smc);
    const uint32_t mbar = sb;
    const uint32_t tiles = sb + 1024;

    const int tid  = threadIdx.x;
    const int lane = tid & 31;
    const int warp = tid >> 5;
    const int wm = warp & 1;
    const int wn = warp >> 1;
    const int m0 = blockIdx.y * 128;
    const int n0 = blockIdx.x * 128;
    const int g  = lane >> 3;
    const int lr = lane & 7;
    const int gm = lane >> 2;
    const int gk = lane & 3;

    const int NI = K / 64;

    if (tid == 0) {
        #pragma unroll
        for (int s = 0; s < GS; s++) mbar_init(mbar + 8 * s, 1);
    }
    __syncthreads();

    auto prod = [&](int kt, int s) {
        uint32_t bar = mbar + 8 * s;
        mbar_expect_tx(bar, GSTG);
        tma2d(tiles + s * GSTG,        &mA, kt * 64, m0, bar);
        tma2d(tiles + s * GSTG + GA_B, &mB, kt * 64, n0, bar);
    };
    if (tid == 0) { prod(0, 0); prod(1, 1); prod(2, 2); }

    uint32_t arow[4], brow[2];
    #pragma unroll
    for (int i = 0; i < 4; i++)
        arow[i] = (uint32_t)((wm * 64 + 16 * i + (g & 1) * 8 + lr) * 128);
    #pragma unroll
    for (int jj = 0; jj < 2; jj++)
        brow[jj] = (uint32_t)(GA_B + (wn * 32 + 16 * jj + (g >> 1) * 8 + lr) * 128);

    float acc[16][4];
    #pragma unroll
    for (int t = 0; t < 16; t++)
        #pragma unroll
        for (int r = 0; r < 4; r++) acc[t][r] = 0.f;

    for (int it = 0; it < NI; it++) {
        const int s = it % GS;
        const uint32_t ph = (uint32_t)((it / GS) & 1);
        mbar_wait(mbar + 8 * s, ph);

        const uint32_t stg = tiles + s * GSTG;
        #pragma unroll
        for (int ks = 0; ks < 4; ks++) {
            uint32_t af[4][4];
            const uint32_t ag = (uint32_t)(((2 * ks + (g >> 1)) ^ lr) << 4);
            #pragma unroll
            for (int i = 0; i < 4; i++)
                ldsm4(af[i], stg + arow[i] + ag);
            uint32_t bf[2][4];
            const uint32_t bg = (uint32_t)(((2 * ks + (g & 1)) ^ lr) << 4);
            #pragma unroll
            for (int jj = 0; jj < 2; jj++)
                ldsm4(bf[jj], stg + brow[jj] + bg);

            #pragma unroll
            for (int i = 0; i < 4; i++)
                #pragma unroll
                for (int jj = 0; jj < 2; jj++) {
                    mma_f16(acc[i * 4 + 2 * jj],     af[i], &bf[jj][0]);
                    mma_f16(acc[i * 4 + 2 * jj + 1], af[i], &bf[jj][2]);
                }
        }
        __syncthreads();
        if (tid == 0 && it + GS < NI) prod(it + GS, s);
    }

    #pragma unroll
    for (int i = 0; i < 4; i++) {
        #pragma unroll
        for (int nn = 0; nn < 4; nn++) {
            float* a = acc[i * 4 + nn];
            int r = m0 + wm * 64 + 16 * i + gm;
            int c = n0 + wn * 32 + 8 * nn + (gk << 1);
            float2 v0 = {a[0], a[1]};
            float2 v1 = {a[2], a[3]};
            *(float2*)(C + (size_t)r * N + c) = v0;
            *(float2*)(C + (size_t)(r + 8) * N + c) = v1;
        }
    }
}

// ---------------------------------------------------------------------------
// TMA fp16 causal flash attention (R12 version, proven best).
// ---------------------------------------------------------------------------
#define AKT_B 8192
#define ASTG (2*AKT_B)                      // K+V = 16384
#define AST 3
#define ATTN_SMEM (1024 + AST*ASTG)         // 50176

__global__ __launch_bounds__(256, 2) void attn_tma(
    const __grid_constant__ CUtensorMap mK,
    const __grid_constant__ CUtensorMap mV,
    float kscale)
{
    const int bh = blockIdx.y;
    const int q0 = (gridDim.x - 1 - blockIdx.x) * 128;
    const int b = bh >> 4, h = bh & 15;
    const int tid = threadIdx.x;
    const int lane = tid & 31;
    const int w = tid >> 5;
    const int gm = lane >> 2;
    const int gk = lane & 3;
    const int g  = lane >> 3;
    const int lr = lane & 7;

    const __half* Qp = g_qh + (size_t)bh * TT * DD;

    extern __shared__ __align__(128) char smc[];
    uint32_t sb = (uint32_t)__cvta_generic_to_shared(smc);
    const uint32_t mbar = sb;

    const int rowA = q0 + w * 16 + gm;
    const int wrow_lo = q0 + w * 16;
    const int wrow_hi = wrow_lo + 15;

    const int ntiles = (q0 + 128) / 64;

    if (tid == 0) {
        #pragma unroll
        for (int s = 0; s < AST; s++) mbar_init(mbar + 8 * s, 1);
    }
    __syncthreads();

    const uint32_t tiles_u32 = sb + 1024;
    auto prod = [&](int jt, int s) {
        uint32_t bar = mbar + 8 * s;
        mbar_expect_tx(bar, ASTG);
        tma3d(tiles_u32 + s * ASTG,         &mK, 0, jt * 64, bh, bar);
        tma3d(tiles_u32 + s * ASTG + AKT_B, &mV, jt * 64, 0, bh, bar);
    };
    if (tid == 0) {
        prod(0, 0);
        prod(1, 1);
        if (ntiles > 2) prod(2, 2);
    }

    uint32_t qf[4][4];
    #pragma unroll
    for (int s = 0; s < 4; s++) {
        const __half* r0 = Qp + (size_t)rowA * DD + 16 * s + 2 * gk;
        const __half* r1 = Qp + (size_t)(rowA + 8) * DD + 16 * s + 2 * gk;
        qf[s][0] = *(const uint32_t*)r0;
        qf[s][1] = *(const uint32_t*)r1;
        qf[s][2] = *(const uint32_t*)(r0 + 8);
        qf[s][3] = *(const uint32_t*)(r1 + 8);
    }

    const uint32_t lrowoff = (uint32_t)(((g >> 1) * 8 + lr) * 128);

    float o[8][4];
    #pragma unroll
    for (int n = 0; n < 8; n++)
        #pragma unroll
        for (int r = 0; r < 4; r++) o[n][r] = 0.f;
    float mA = -1e30f, mB = -1e30f, lA = 0.f, lB = 0.f;

    for (int jt = 0; jt < ntiles; jt++) {
        const int st = jt % AST;
        mbar_wait(mbar + 8 * st, (uint32_t)((jt / AST) & 1));

        const uint32_t Ks = tiles_u32 + st * ASTG;
        const uint32_t Vs = Ks + AKT_B;
        const int j0 = jt * 64;

        if (j0 <= wrow_hi) {
            float sf[8][4];
            #pragma unroll
            for (int j = 0; j < 8; j++)
                #pragma unroll
                for (int r = 0; r < 4; r++) sf[j][r] = 0.f;
            #pragma unroll
            for (int s = 0; s < 4; s++) {
                const uint32_t bg = (uint32_t)(((2 * s + (g & 1)) ^ lr) << 4);
                #pragma unroll
                for (int jp = 0; jp < 4; jp++) {
                    uint32_t bf[4];
                    ldsm4(bf, Ks + (uint32_t)(16 * jp * 128) + lrowoff + bg);
                    mma_f16(sf[2 * jp],     qf[s], &bf[0]);
                    mma_f16(sf[2 * jp + 1], qf[s], &bf[2]);
                }
            }

            const bool needmask = (j0 + 63 > wrow_lo);
            float mxA = -1e30f, mxB = -1e30f;
            #pragma unroll
            for (int j = 0; j < 8; j++) {
                #pragma unroll
                for (int e = 0; e < 2; e++) {
                    int col = j0 + 8 * j + 2 * gk + e;
                    float v0 = sf[j][e] * kscale;
                    float v1 = sf[j][2 + e] * kscale;
                    if (needmask) {
                        if (col > rowA)     v0 = -1e30f;
                        if (col > rowA + 8) v1 = -1e30f;
                    }
                    sf[j][e] = v0; sf[j][2 + e] = v1;
                    mxA = fmaxf(mxA, v0); mxB = fmaxf(mxB, v1);
                }
            }
            mxA = fmaxf(mxA, __shfl_xor_sync(0xffffffffu, mxA, 1));
            mxA = fmaxf(mxA, __shfl_xor_sync(0xffffffffu, mxA, 2));
            mxB = fmaxf(mxB, __shfl_xor_sync(0xffffffffu, mxB, 1));
            mxB = fmaxf(mxB, __shfl_xor_sync(0xffffffffu, mxB, 2));

            float nmA = fmaxf(mA, mxA), nmB = fmaxf(mB, mxB);
            float aA = ex2(mA - nmA), aB = ex2(mB - nmB);
            mA = nmA; mB = nmB;

            #pragma unroll
            for (int n = 0; n < 8; n++) {
                o[n][0] *= aA; o[n][1] *= aA;
                o[n][2] *= aB; o[n][3] *= aB;
            }
            lA *= aA; lB *= aB;

            uint32_t phl[8][2];
            float slA = 0.f, slB = 0.f;
            #pragma unroll
            for (int j = 0; j < 8; j++) {
                float p0 = ex2(sf[j][0] - mA);
                float p1 = ex2(sf[j][1] - mA);
                float p2 = ex2(sf[j][2] - mB);
                float p3 = ex2(sf[j][3] - mB);
                slA += p0 + p1; slB += p2 + p3;
                __half2 h01 = __floats2half2_rn(p0, p1);
                __half2 h23 = __floats2half2_rn(p2, p3);
                phl[j][0] = *(const uint32_t*)&h01;
                phl[j][1] = *(const uint32_t*)&h23;
            }
            slA += __shfl_xor_sync(0xffffffffu, slA, 1);
            slA += __shfl_xor_sync(0xffffffffu, slA, 2);
            slB += __shfl_xor_sync(0xffffffffu, slB, 1);
            slB += __shfl_xor_sync(0xffffffffu, slB, 2);
            lA += slA; lB += slB;

            #pragma unroll
            for (int s2 = 0; s2 < 4; s2++) {
                uint32_t af[4] = { phl[2 * s2][0], phl[2 * s2][1],
                                   phl[2 * s2 + 1][0], phl[2 * s2 + 1][1] };
                const uint32_t vg = (uint32_t)(((2 * s2 + (g & 1)) ^ lr) << 4);
                #pragma unroll
                for (int jp = 0; jp < 4; jp++) {
                    uint32_t bf[4];
                    ldsm4(bf, Vs + (uint32_t)(16 * jp * 128) + lrowoff + vg);
                    mma_f16(o[2 * jp],     af, &bf[0]);
                    mma_f16(o[2 * jp + 1], af, &bf[2]);
                }
            }
        }
        __syncthreads();
        if (tid == 0 && jt + AST < ntiles) prod(jt + AST, st);
    }

    float invA = 1.f / lA, invB = 1.f / lB;
    __half* dstA = g_atth + (size_t)(b * TT + rowA) * CC + h * DD;
    __half* dstB = g_atth + (size_t)(b * TT + rowA + 8) * CC + h * DD;
    #pragma unroll
    for (int n = 0; n < 8; n++) {
        int cix = 8 * n + 2 * gk;
        __half2 v0 = __floats2half2_rn(o[n][0] * invA, o[n][1] * invA);
        __half2 v1 = __floats2half2_rn(o[n][2] * invB, o[n][3] * invB);
        *(uint32_t*)(dstA + cix) = *(uint32_t*)&v0;
        *(uint32_t*)(dstB + cix) = *(uint32_t*)&v1;
    }
}

// ---------------------------------------------------------------------------
// Host: tensor-map encode via driver entry point
// ---------------------------------------------------------------------------
typedef CUresult (*PFN_tmap_encode)(
    CUtensorMap*, CUtensorMapDataType, cuuint32_t, void*,
    const cuuint64_t*, const cuuint64_t*, const cuuint32_t*, const cuuint32_t*,
    CUtensorMapInterleave, CUtensorMapSwizzle, CUtensorMapL2promotion,
    CUtensorMapFloatOOBfill);

static PFN_tmap_encode get_encoder() {
    void* fn = nullptr;
    cudaDriverEntryPointQueryResult qr;
    cudaGetDriverEntryPoint("cuTensorMapEncodeTiled", &fn, cudaEnableDefault, &qr);
    return (PFN_tmap_encode)fn;
}

static void enc2d(PFN_tmap_encode f, CUtensorMap* m, void* base,
                  uint64_t d0, uint64_t d1, uint32_t b0, uint32_t b1) {
    cuuint64_t dims[2] = {d0, d1};
    cuuint64_t str[1]  = {d0 * 2};
    cuuint32_t box[2]  = {b0, b1};
    cuuint32_t es[2]   = {1, 1};
    f(m, CU_TENSOR_MAP_DATA_TYPE_FLOAT16, 2, base, dims, str, box, es,
      CU_TENSOR_MAP_INTERLEAVE_NONE, CU_TENSOR_MAP_SWIZZLE_128B,
      CU_TENSOR_MAP_L2_PROMOTION_L2_128B, CU_TENSOR_MAP_FLOAT_OOB_FILL_NONE);
}

static void enc3d(PFN_tmap_encode f, CUtensorMap* m, void* base,
                  uint64_t d0, uint64_t d1, uint64_t d2,
                  uint32_t b0, uint32_t b1) {
    cuuint64_t dims[3] = {d0, d1, d2};
    cuuint64_t str[2]  = {d0 * 2, d0 * d1 * 2};
    cuuint32_t box[3]  = {b0, b1, 1};
    cuuint32_t es[3]   = {1, 1, 1};
    f(m, CU_TENSOR_MAP_DATA_TYPE_FLOAT16, 3, base, dims, str, box, es,
      CU_TENSOR_MAP_INTERLEAVE_NONE, CU_TENSOR_MAP_SWIZZLE_128B,
      CU_TENSOR_MAP_L2_PROMOTION_L2_128B, CU_TENSOR_MAP_FLOAT_OOB_FILL_NONE);
}

// ---------------------------------------------------------------------------
// Launch
// ---------------------------------------------------------------------------
extern "C" void kernel_launch(void* const* d_in, const int* in_sizes, int n_in,
                              void* d_out, int out_size)
{
    const float* x     = (const float*)d_in[0];
    const float* cosp  = (const float*)d_in[1];
    const float* sinp  = (const float*)d_in[2];
    const float* w_qkv = (const float*)d_in[3];
    const float* w_out = (const float*)d_in[4];
    float* out = (float*)d_out;

    __half *p_xh, *p_wqkvh, *p_wouth, *p_kh, *p_vh, *p_atth;
    cudaGetSymbolAddress((void**)&p_xh,    g_xh);
    cudaGetSymbolAddress((void**)&p_wqkvh, g_wqkvh);
    cudaGetSymbolAddress((void**)&p_wouth, g_wouth);
    cudaGetSymbolAddress((void**)&p_kh,    g_kh);
    cudaGetSymbolAddress((void**)&p_vh,    g_vh);
    cudaGetSymbolAddress((void**)&p_atth,  g_atth);

    PFN_tmap_encode enc = get_encoder();

    CUtensorMap mX, mWqkv, mAtt, mWout, mK, mV;
    enc2d(enc, &mX,    p_xh,    CC, MM,   64, 128);
    enc2d(enc, &mWqkv, p_wqkvh, CC, NQKV, 64, 128);
    enc2d(enc, &mAtt,  p_atth,  CC, MM,   64, 128);
    enc2d(enc, &mWout, p_wouth, CC, CC,   64, 128);
    enc3d(enc, &mK, p_kh, DD, TT, BB * HH, 64, 64);
    enc3d(enc, &mV, p_vh, TT, DD, BB * HH, 64, 64);

    cudaFuncSetAttribute(gemm_qkv,
                         cudaFuncAttributeMaxDynamicSharedMemorySize, GEMM_SMEM);
    cudaFuncSetAttribute(gemm_out,
                         cudaFuncAttributeMaxDynamicSharedMemorySize, GEMM_SMEM);
    cudaFuncSetAttribute(attn_tma,
                         cudaFuncAttributeMaxDynamicSharedMemorySize, ATTN_SMEM);

    // 0) fp32 -> fp16 converts
    cvt_h<<<(MM * CC) / (8 * 256), 256>>>(x, p_xh, MM * CC);
    cvt_h<<<(NQKV * CC) / (8 * 256), 256>>>(w_qkv, p_wqkvh, NQKV * CC);
    cvt_h<<<(CC * CC) / (8 * 256), 256>>>(w_out, p_wouth, CC * CC);

    // 1) qkv GEMM with fused RoPE + scatter (writes g_qh/g_kh/g_vh directly)
    {
        dim3 grid(NQKV / 128, MM / 128);
        gemm_qkv<<<grid, 256, GEMM_SMEM>>>(mX, mWqkv, cosp, sinp, NQKV, CC);
    }

    // 2) TMA fp16 causal flash attention
    {
        dim3 grid(TT / 128, BB * HH);
        attn_tma<<<grid, 256, ATTN_SMEM>>>(mK, mV, 0.125f * 1.44269504f);
    }

    // 3) out = att @ w_out^T (fp32 out)
    {
        dim3 grid(CC / 128, MM / 128);
        gemm_out<<<grid, 256, GEMM_SMEM>>>(mAtt, mWout, out, CC, CC);
    }
}

// round 15
// speedup vs baseline: 1.1021x; 1.0346x over previous
#include <cuda_runtime.h>
#include <cuda.h>
#include <cuda_fp16.h>
#include <cstdint>

// Problem constants
#define BB 2
#define TT 2048
#define HH 16
#define DD 64
#define CC 1024
#define MM (BB*TT)        // 4096 rows
#define NQKV (3*CC)       // 3072

// Scratch (device globals -- no allocation allowed)
__device__ __half g_xh[MM * CC];           // x in fp16
__device__ __half g_wqkvh[NQKV * CC];      // w_qkv in fp16
__device__ __half g_wouth[CC * CC];        // w_out in fp16
__device__ __half g_qh[BB*HH*TT*DD];       // [bh][t][d] fp16 (post-RoPE)
__device__ __half g_kh[BB*HH*TT*DD];       // [bh][t][d] fp16 (post-RoPE)
__device__ __half g_vh[BB*HH*DD*TT];       // [bh][d][t] fp16 (d-major)
__device__ __half g_atth[MM * CC];         // attention out, fp16 [B,T,C]

__device__ __forceinline__ float ex2(float x) {
    float y;
    asm("ex2.approx.ftz.f32 %0, %1;" : "=f"(y) : "f"(x));
    return y;
}

__device__ __forceinline__ void mma_f16(float* d, const uint32_t* a, const uint32_t* b) {
    asm volatile(
        "mma.sync.aligned.m16n8k16.row.col.f32.f16.f16.f32 "
        "{%0,%1,%2,%3},{%4,%5,%6,%7},{%8,%9},{%0,%1,%2,%3};\n"
        : "+f"(d[0]), "+f"(d[1]), "+f"(d[2]), "+f"(d[3])
        : "r"(a[0]), "r"(a[1]), "r"(a[2]), "r"(a[3]), "r"(b[0]), "r"(b[1]));
}

__device__ __forceinline__ void ldsm4(uint32_t* r, uint32_t addr) {
    asm volatile("ldmatrix.sync.aligned.m8n8.x4.shared.b16 {%0,%1,%2,%3}, [%4];"
                 : "=r"(r[0]), "=r"(r[1]), "=r"(r[2]), "=r"(r[3]) : "r"(addr));
}

__device__ __forceinline__ void mbar_init(uint32_t addr, uint32_t cnt) {
    asm volatile("mbarrier.init.shared.b64 [%0], %1;" :: "r"(addr), "r"(cnt) : "memory");
}
__device__ __forceinline__ void mbar_expect_tx(uint32_t addr, uint32_t bytes) {
    asm volatile("mbarrier.arrive.expect_tx.shared.b64 _, [%0], %1;"
                 :: "r"(addr), "r"(bytes) : "memory");
}
__device__ __forceinline__ void mbar_wait(uint32_t addr, uint32_t parity) {
    asm volatile(
        "{\n\t.reg .pred P;\n"
        "W:\n\tmbarrier.try_wait.parity.acquire.cta.shared::cta.b64 P, [%0], %1, 0x989680;\n"
        "\t@P bra D;\n\tbra W;\nD:\n\t}"
        :: "r"(addr), "r"(parity) : "memory");
}
__device__ __forceinline__ void tma2d(uint32_t smem, const CUtensorMap* map,
                                      int x, int y, uint32_t bar) {
    asm volatile(
        "cp.async.bulk.tensor.2d.shared::cta.global.tile.mbarrier::complete_tx::bytes "
        "[%0], [%1, {%2, %3}], [%4];"
        :: "r"(smem), "l"(map), "r"(x), "r"(y), "r"(bar) : "memory");
}
__device__ __forceinline__ void tma3d(uint32_t smem, const CUtensorMap* map,
                                      int x, int y, int z, uint32_t bar) {
    asm volatile(
        "cp.async.bulk.tensor.3d.shared::cta.global.tile.mbarrier::complete_tx::bytes "
        "[%0], [%1, {%2, %3, %4}], [%5];"
        :: "r"(smem), "l"(map), "r"(x), "r"(y), "r"(z), "r"(bar) : "memory");
}

// ---------------------------------------------------------------------------
// Merged fp32 -> fp16 convert for x, w_qkv, w_out in ONE launch.
// Region boundaries all divisible by 8.
// ---------------------------------------------------------------------------
#define N1 (MM*CC)          // 4194304
#define N2 (NQKV*CC)        // 3145728
#define N3 (CC*CC)          // 1048576
#define NTOT (N1+N2+N3)     // 8388608

__global__ __launch_bounds__(256) void cvt_all(
    const float* __restrict__ x,
    const float* __restrict__ wq,
    const float* __restrict__ wo)
{
    int i = (blockIdx.x * blockDim.x + threadIdx.x) * 8;
    if (i >= NTOT) return;
    const float* src;
    __half* dst;
    if (i < N1)            { src = x  + i;             dst = g_xh    + i; }
    else if (i < N1 + N2)  { src = wq + (i - N1);      dst = g_wqkvh + (i - N1); }
    else                   { src = wo + (i - N1 - N2); dst = g_wouth + (i - N1 - N2); }

    float4 v0 = *(const float4*)(src);
    float4 v1 = *(const float4*)(src + 4);
    __half2 h0 = __floats2half2_rn(v0.x, v0.y);
    __half2 h1 = __floats2half2_rn(v0.z, v0.w);
    __half2 h2 = __floats2half2_rn(v1.x, v1.y);
    __half2 h3 = __floats2half2_rn(v1.z, v1.w);
    uint4 o;
    o.x = *(uint32_t*)&h0; o.y = *(uint32_t*)&h1;
    o.z = *(uint32_t*)&h2; o.w = *(uint32_t*)&h3;
    *(uint4*)dst = o;
}

// ---------------------------------------------------------------------------
// Shared GEMM pipeline pieces
// ---------------------------------------------------------------------------
#define GS 3
#define GA_B 16384
#define GSTG (2*GA_B)                       // 32768 per stage (A+B)
#define GEMM_SMEM (1024 + GS*GSTG)          // 99328
#define CPITCH 136                          // halves; epilogue smem tile pitch

// ---------------------------------------------------------------------------
// qkv GEMM with fused RoPE + scatter epilogue.
// ---------------------------------------------------------------------------
__global__ __launch_bounds__(256, 2) void gemm_qkv(
    const __grid_constant__ CUtensorMap mA,
    const __grid_constant__ CUtensorMap mB,
    const float* __restrict__ cosp, const float* __restrict__ sinp,
    int N, int K)
{
    extern __shared__ __align__(128) char smc[];
    uint32_t sb = (uint32_t)__cvta_generic_to_shared(smc);
    const uint32_t mbar = sb;
    const uint32_t tiles = sb + 1024;

    const int tid  = threadIdx.x;
    const int lane = tid & 31;
    const int warp = tid >> 5;
    const int wm = warp & 1;
    const int wn = warp >> 1;
    const int m0 = blockIdx.y * 128;
    const int n0 = blockIdx.x * 128;
    const int g  = lane >> 3;
    const int lr = lane & 7;
    const int gm = lane >> 2;
    const int gk = lane & 3;

    const int NI = K / 64;

    if (tid == 0) {
        #pragma unroll
        for (int s = 0; s < GS; s++) mbar_init(mbar + 8 * s, 1);
    }
    __syncthreads();

    auto prod = [&](int kt, int s) {
        uint32_t bar = mbar + 8 * s;
        mbar_expect_tx(bar, GSTG);
        tma2d(tiles + s * GSTG,        &mA, kt * 64, m0, bar);
        tma2d(tiles + s * GSTG + GA_B, &mB, kt * 64, n0, bar);
    };
    if (tid == 0) { prod(0, 0); prod(1, 1); prod(2, 2); }

    uint32_t arow[4], brow[2];
    #pragma unroll
    for (int i = 0; i < 4; i++)
        arow[i] = (uint32_t)((wm * 64 + 16 * i + (g & 1) * 8 + lr) * 128);
    #pragma unroll
    for (int jj = 0; jj < 2; jj++)
        brow[jj] = (uint32_t)(GA_B + (wn * 32 + 16 * jj + (g >> 1) * 8 + lr) * 128);

    float acc[16][4];
    #pragma unroll
    for (int t = 0; t < 16; t++)
        #pragma unroll
        for (int r = 0; r < 4; r++) acc[t][r] = 0.f;

    for (int it = 0; it < NI; it++) {
        const int s = it % GS;
        const uint32_t ph = (uint32_t)((it / GS) & 1);
        mbar_wait(mbar + 8 * s, ph);

        const uint32_t stg = tiles + s * GSTG;
        #pragma unroll
        for (int ks = 0; ks < 4; ks++) {
            uint32_t af[4][4];
            const uint32_t ag = (uint32_t)(((2 * ks + (g >> 1)) ^ lr) << 4);
            #pragma unroll
            for (int i = 0; i < 4; i++)
                ldsm4(af[i], stg + arow[i] + ag);
            uint32_t bf[2][4];
            const uint32_t bg = (uint32_t)(((2 * ks + (g & 1)) ^ lr) << 4);
            #pragma unroll
            for (int jj = 0; jj < 2; jj++)
                ldsm4(bf[jj], stg + brow[jj] + bg);

            #pragma unroll
            for (int i = 0; i < 4; i++)
                #pragma unroll
                for (int jj = 0; jj < 2; jj++) {
                    mma_f16(acc[i * 4 + 2 * jj],     af[i], &bf[jj][0]);
                    mma_f16(acc[i * 4 + 2 * jj + 1], af[i], &bf[jj][2]);
                }
        }
        __syncthreads();
        if (tid == 0 && it + GS < NI) prod(it + GS, s);
    }

    // ---- fused epilogue: park C tile in smem (pipeline smem is free) ----
    __half* cs = (__half*)(smc + 1024);
    #pragma unroll
    for (int i = 0; i < 4; i++) {
        #pragma unroll
        for (int nn = 0; nn < 4; nn++) {
            float* a = acc[i * 4 + nn];
            int r  = wm * 64 + 16 * i + gm;
            int cp = wn * 32 + 8 * nn + (gk << 1);
            __half2 v0 = __floats2half2_rn(a[0], a[1]);
            __half2 v1 = __floats2half2_rn(a[2], a[3]);
            *(uint32_t*)(cs + r * CPITCH + cp)       = *(uint32_t*)&v0;
            *(uint32_t*)(cs + (r + 8) * CPITCH + cp) = *(uint32_t*)&v1;
        }
    }
    __syncthreads();

    // ---- scatter: thread = one tile column x 64 rows ----
    const int colg  = tid & 127;           // local col
    const int rhalf = tid >> 7;            // 0/1
    const int c   = n0 + colg;             // global f index 0..3071
    const int reg = c >> 10;               // 0=q 1=k 2=v
    const int hd  = c & 1023;
    const int h   = hd >> 6, d = hd & 63;
    const int mb  = m0 + rhalf * 64;       // first global row
    const int b   = mb >> 11;
    const int lr0 = rhalf * 64;            // first local row

    if (reg < 2) {
        const int pcol = colg ^ 32;        // RoPE partner column (d +/- 32)
        __half* dst = (reg == 0 ? g_qh : g_kh)
                      + ((size_t)(b * HH + h) * TT) * DD + d;
        const float sgn = (d < 32) ? -1.f : 1.f;
        for (int rr = 0; rr < 64; rr++) {
            int t = (mb + rr) & (TT - 1);
            float cv = cosp[t * DD + d];
            float sv = sinp[t * DD + d];
            float xm = __half2float(cs[(lr0 + rr) * CPITCH + colg]);
            float xp = __half2float(cs[(lr0 + rr) * CPITCH + pcol]);
            dst[(size_t)t * DD] = __float2half(xm * cv + sgn * xp * sv);
        }
    } else {
        __half* dst = g_vh + ((size_t)(b * HH + h) * DD + d) * TT;
        for (int rr = 0; rr < 64; rr += 8) {
            __half tmp[8];
            #pragma unroll
            for (int k = 0; k < 8; k++)
                tmp[k] = cs[(lr0 + rr + k) * CPITCH + colg];
            int t = (mb + rr) & (TT - 1);
            *(uint4*)(dst + t) = *(uint4*)tmp;
        }
    }
}

// ---------------------------------------------------------------------------
// Output-projection GEMM: C = A @ B^T, fp32 out.
// ---------------------------------------------------------------------------
__global__ __launch_bounds__(256, 2) void gemm_out(
    const __grid_constant__ CUtensorMap mA,
    const __grid_constant__ CUtensorMap mB,
    float* __restrict__ C, int N, int K)
{
    extern __shared__ __align__(128) char smc[];
    uint32_t sb = (uint32_t)__cvta_generic_to_shared(smc);
    const uint32_t mbar = sb;
    const uint32_t tiles = sb + 1024;

    const int tid  = threadIdx.x;
    const int lane = tid & 31;
    const int warp = tid >> 5;
    const int wm = warp & 1;
    const int wn = warp >> 1;
    const int m0 = blockIdx.y * 128;
    const int n0 = blockIdx.x * 128;
    const int g  = lane >> 3;
    const int lr = lane & 7;
    const int gm = lane >> 2;
    const int gk = lane & 3;

    const int NI = K / 64;

    if (tid == 0) {
        #pragma unroll
        for (int s = 0; s < GS; s++) mbar_init(mbar + 8 * s, 1);
    }
    __syncthreads();

    auto prod = [&](int kt, int s) {
        uint32_t bar = mbar + 8 * s;
        mbar_expect_tx(bar, GSTG);
        tma2d(tiles + s * GSTG,        &mA, kt * 64, m0, bar);
        tma2d(tiles + s * GSTG + GA_B, &mB, kt * 64, n0, bar);
    };
    if (tid == 0) { prod(0, 0); prod(1, 1); prod(2, 2); }

    uint32_t arow[4], brow[2];
    #pragma unroll
    for (int i = 0; i < 4; i++)
        arow[i] = (uint32_t)((wm * 64 + 16 * i + (g & 1) * 8 + lr) * 128);
    #pragma unroll
    for (int jj = 0; jj < 2; jj++)
        brow[jj] = (uint32_t)(GA_B + (wn * 32 + 16 * jj + (g >> 1) * 8 + lr) * 128);

    float acc[16][4];
    #pragma unroll
    for (int t = 0; t < 16; t++)
        #pragma unroll
        for (int r = 0; r < 4; r++) acc[t][r] = 0.f;

    for (int it = 0; it < NI; it++) {
        const int s = it % GS;
        const uint32_t ph = (uint32_t)((it / GS) & 1);
        mbar_wait(mbar + 8 * s, ph);

        const uint32_t stg = tiles + s * GSTG;
        #pragma unroll
        for (int ks = 0; ks < 4; ks++) {
            uint32_t af[4][4];
            const uint32_t ag = (uint32_t)(((2 * ks + (g >> 1)) ^ lr) << 4);
            #pragma unroll
            for (int i = 0; i < 4; i++)
                ldsm4(af[i], stg + arow[i] + ag);
            uint32_t bf[2][4];
            const uint32_t bg = (uint32_t)(((2 * ks + (g & 1)) ^ lr) << 4);
            #pragma unroll
            for (int jj = 0; jj < 2; jj++)
                ldsm4(bf[jj], stg + brow[jj] + bg);

            #pragma unroll
            for (int i = 0; i < 4; i++)
                #pragma unroll
                for (int jj = 0; jj < 2; jj++) {
                    mma_f16(acc[i * 4 + 2 * jj],     af[i], &bf[jj][0]);
                    mma_f16(acc[i * 4 + 2 * jj + 1], af[i], &bf[jj][2]);
                }
        }
        __syncthreads();
        if (tid == 0 && it + GS < NI) prod(it + GS, s);
    }

    #pragma unroll
    for (int i = 0; i < 4; i++) {
        #pragma unroll
        for (int nn = 0; nn < 4; nn++) {
            float* a = acc[i * 4 + nn];
            int r = m0 + wm * 64 + 16 * i + gm;
            int c = n0 + wn * 32 + 8 * nn + (gk << 1);
            float2 v0 = {a[0], a[1]};
            float2 v1 = {a[2], a[3]};
            *(float2*)(C + (size_t)r * N + c) = v0;
            *(float2*)(C + (size_t)(r + 8) * N + c) = v1;
        }
    }
}

// ---------------------------------------------------------------------------
// TMA fp16 causal flash attention (R12 version, proven best).
// ---------------------------------------------------------------------------
#define AKT_B 8192
#define ASTG (2*AKT_B)                      // K+V = 16384
#define AST 3
#define ATTN_SMEM (1024 + AST*ASTG)         // 50176

__global__ __launch_bounds__(256, 2) void attn_tma(
    const __grid_constant__ CUtensorMap mK,
    const __grid_constant__ CUtensorMap mV,
    float kscale)
{
    const int bh = blockIdx.y;
    const int q0 = (gridDim.x - 1 - blockIdx.x) * 128;
    const int b = bh >> 4, h = bh & 15;
    const int tid = threadIdx.x;
    const int lane = tid & 31;
    const int w = tid >> 5;
    const int gm = lane >> 2;
    const int gk = lane & 3;
    const int g  = lane >> 3;
    const int lr = lane & 7;

    const __half* Qp = g_qh + (size_t)bh * TT * DD;

    extern __shared__ __align__(128) char smc[];
    uint32_t sb = (uint32_t)__cvta_generic_to_shared(smc);
    const uint32_t mbar = sb;

    const int rowA = q0 + w * 16 + gm;
    const int wrow_lo = q0 + w * 16;
    const int wrow_hi = wrow_lo + 15;

    const int ntiles = (q0 + 128) / 64;

    if (tid == 0) {
        #pragma unroll
        for (int s = 0; s < AST; s++) mbar_init(mbar + 8 * s, 1);
    }
    __syncthreads();

    const uint32_t tiles_u32 = sb + 1024;
    auto prod = [&](int jt, int s) {
        uint32_t bar = mbar + 8 * s;
        mbar_expect_tx(bar, ASTG);
        tma3d(tiles_u32 + s * ASTG,         &mK, 0, jt * 64, bh, bar);
        tma3d(tiles_u32 + s * ASTG + AKT_B, &mV, jt * 64, 0, bh, bar);
    };
    if (tid == 0) {
        prod(0, 0);
        prod(1, 1);
        if (ntiles > 2) prod(2, 2);
    }

    uint32_t qf[4][4];
    #pragma unroll
    for (int s = 0; s < 4; s++) {
        const __half* r0 = Qp + (size_t)rowA * DD + 16 * s + 2 * gk;
        const __half* r1 = Qp + (size_t)(rowA + 8) * DD + 16 * s + 2 * gk;
        qf[s][0] = *(const uint32_t*)r0;
        qf[s][1] = *(const uint32_t*)r1;
        qf[s][2] = *(const uint32_t*)(r0 + 8);
        qf[s][3] = *(const uint32_t*)(r1 + 8);
    }

    const uint32_t lrowoff = (uint32_t)(((g >> 1) * 8 + lr) * 128);

    float o[8][4];
    #pragma unroll
    for (int n = 0; n < 8; n++)
        #pragma unroll
        for (int r = 0; r < 4; r++) o[n][r] = 0.f;
    float mA = -1e30f, mB = -1e30f, lA = 0.f, lB = 0.f;

    for (int jt = 0; jt < ntiles; jt++) {
        const int st = jt % AST;
        mbar_wait(mbar + 8 * st, (uint32_t)((jt / AST) & 1));

        const uint32_t Ks = tiles_u32 + st * ASTG;
        const uint32_t Vs = Ks + AKT_B;
        const int j0 = jt * 64;

        if (j0 <= wrow_hi) {
            float sf[8][4];
            #pragma unroll
            for (int j = 0; j < 8; j++)
                #pragma unroll
                for (int r = 0; r < 4; r++) sf[j][r] = 0.f;
            #pragma unroll
            for (int s = 0; s < 4; s++) {
                const uint32_t bg = (uint32_t)(((2 * s + (g & 1)) ^ lr) << 4);
                #pragma unroll
                for (int jp = 0; jp < 4; jp++) {
                    uint32_t bf[4];
                    ldsm4(bf, Ks + (uint32_t)(16 * jp * 128) + lrowoff + bg);
                    mma_f16(sf[2 * jp],     qf[s], &bf[0]);
                    mma_f16(sf[2 * jp + 1], qf[s], &bf[2]);
                }
            }

            const bool needmask = (j0 + 63 > wrow_lo);
            float mxA = -1e30f, mxB = -1e30f;
            #pragma unroll
            for (int j = 0; j < 8; j++) {
                #pragma unroll
                for (int e = 0; e < 2; e++) {
                    int col = j0 + 8 * j + 2 * gk + e;
                    float v0 = sf[j][e] * kscale;
                    float v1 = sf[j][2 + e] * kscale;
                    if (needmask) {
                        if (col > rowA)     v0 = -1e30f;
                        if (col > rowA + 8) v1 = -1e30f;
                    }
                    sf[j][e] = v0; sf[j][2 + e] = v1;
                    mxA = fmaxf(mxA, v0); mxB = fmaxf(mxB, v1);
                }
            }
            mxA = fmaxf(mxA, __shfl_xor_sync(0xffffffffu, mxA, 1));
            mxA = fmaxf(mxA, __shfl_xor_sync(0xffffffffu, mxA, 2));
            mxB = fmaxf(mxB, __shfl_xor_sync(0xffffffffu, mxB, 1));
            mxB = fmaxf(mxB, __shfl_xor_sync(0xffffffffu, mxB, 2));

            float nmA = fmaxf(mA, mxA), nmB = fmaxf(mB, mxB);
            float aA = ex2(mA - nmA), aB = ex2(mB - nmB);
            mA = nmA; mB = nmB;

            #pragma unroll
            for (int n = 0; n < 8; n++) {
                o[n][0] *= aA; o[n][1] *= aA;
                o[n][2] *= aB; o[n][3] *= aB;
            }
            lA *= aA; lB *= aB;

            uint32_t phl[8][2];
            float slA = 0.f, slB = 0.f;
            #pragma unroll
            for (int j = 0; j < 8; j++) {
                float p0 = ex2(sf[j][0] - mA);
                float p1 = ex2(sf[j][1] - mA);
                float p2 = ex2(sf[j][2] - mB);
                float p3 = ex2(sf[j][3] - mB);
                slA += p0 + p1; slB += p2 + p3;
                __half2 h01 = __floats2half2_rn(p0, p1);
                __half2 h23 = __floats2half2_rn(p2, p3);
                phl[j][0] = *(const uint32_t*)&h01;
                phl[j][1] = *(const uint32_t*)&h23;
            }
            slA += __shfl_xor_sync(0xffffffffu, slA, 1);
            slA += __shfl_xor_sync(0xffffffffu, slA, 2);
            slB += __shfl_xor_sync(0xffffffffu, slB, 1);
            slB += __shfl_xor_sync(0xffffffffu, slB, 2);
            lA += slA; lB += slB;

            #pragma unroll
            for (int s2 = 0; s2 < 4; s2++) {
                uint32_t af[4] = { phl[2 * s2][0], phl[2 * s2][1],
                                   phl[2 * s2 + 1][0], phl[2 * s2 + 1][1] };
                const uint32_t vg = (uint32_t)(((2 * s2 + (g & 1)) ^ lr) << 4);
                #pragma unroll
                for (int jp = 0; jp < 4; jp++) {
                    uint32_t bf[4];
                    ldsm4(bf, Vs + (uint32_t)(16 * jp * 128) + lrowoff + vg);
                    mma_f16(o[2 * jp],     af, &bf[0]);
                    mma_f16(o[2 * jp + 1], af, &bf[2]);
                }
            }
        }
        __syncthreads();
        if (tid == 0 && jt + AST < ntiles) prod(jt + AST, st);
    }

    float invA = 1.f / lA, invB = 1.f / lB;
    __half* dstA = g_atth + (size_t)(b * TT + rowA) * CC + h * DD;
    __half* dstB = g_atth + (size_t)(b * TT + rowA + 8) * CC + h * DD;
    #pragma unroll
    for (int n = 0; n < 8; n++) {
        int cix = 8 * n + 2 * gk;
        __half2 v0 = __floats2half2_rn(o[n][0] * invA, o[n][1] * invA);
        __half2 v1 = __floats2half2_rn(o[n][2] * invB, o[n][3] * invB);
        *(uint32_t*)(dstA + cix) = *(uint32_t*)&v0;
        *(uint32_t*)(dstB + cix) = *(uint32_t*)&v1;
    }
}

// ---------------------------------------------------------------------------
// Host: tensor-map encode via driver entry point
// ---------------------------------------------------------------------------
typedef CUresult (*PFN_tmap_encode)(
    CUtensorMap*, CUtensorMapDataType, cuuint32_t, void*,
    const cuuint64_t*, const cuuint64_t*, const cuuint32_t*, const cuuint32_t*,
    CUtensorMapInterleave, CUtensorMapSwizzle, CUtensorMapL2promotion,
    CUtensorMapFloatOOBfill);

static PFN_tmap_encode get_encoder() {
    void* fn = nullptr;
    cudaDriverEntryPointQueryResult qr;
    cudaGetDriverEntryPoint("cuTensorMapEncodeTiled", &fn, cudaEnableDefault, &qr);
    return (PFN_tmap_encode)fn;
}

static void enc2d(PFN_tmap_encode f, CUtensorMap* m, void* base,
                  uint64_t d0, uint64_t d1, uint32_t b0, uint32_t b1) {
    cuuint64_t dims[2] = {d0, d1};
    cuuint64_t str[1]  = {d0 * 2};
    cuuint32_t box[2]  = {b0, b1};
    cuuint32_t es[2]   = {1, 1};
    f(m, CU_TENSOR_MAP_DATA_TYPE_FLOAT16, 2, base, dims, str, box, es,
      CU_TENSOR_MAP_INTERLEAVE_NONE, CU_TENSOR_MAP_SWIZZLE_128B,
      CU_TENSOR_MAP_L2_PROMOTION_L2_128B, CU_TENSOR_MAP_FLOAT_OOB_FILL_NONE);
}

static void enc3d(PFN_tmap_encode f, CUtensorMap* m, void* base,
                  uint64_t d0, uint64_t d1, uint64_t d2,
                  uint32_t b0, uint32_t b1) {
    cuuint64_t dims[3] = {d0, d1, d2};
    cuuint64_t str[2]  = {d0 * 2, d0 * d1 * 2};
    cuuint32_t box[3]  = {b0, b1, 1};
    cuuint32_t es[3]   = {1, 1, 1};
    f(m, CU_TENSOR_MAP_DATA_TYPE_FLOAT16, 3, base, dims, str, box, es,
      CU_TENSOR_MAP_INTERLEAVE_NONE, CU_TENSOR_MAP_SWIZZLE_128B,
      CU_TENSOR_MAP_L2_PROMOTION_L2_128B, CU_TENSOR_MAP_FLOAT_OOB_FILL_NONE);
}

// ---------------------------------------------------------------------------
// Launch
// ---------------------------------------------------------------------------
extern "C" void kernel_launch(void* const* d_in, const int* in_sizes, int n_in,
                              void* d_out, int out_size)
{
    const float* x     = (const float*)d_in[0];
    const float* cosp  = (const float*)d_in[1];
    const float* sinp  = (const float*)d_in[2];
    const float* w_qkv = (const float*)d_in[3];
    const float* w_out = (const float*)d_in[4];
    float* out = (float*)d_out;

    __half *p_xh, *p_wqkvh, *p_wouth, *p_kh, *p_vh, *p_atth;
    cudaGetSymbolAddress((void**)&p_xh,    g_xh);
    cudaGetSymbolAddress((void**)&p_wqkvh, g_wqkvh);
    cudaGetSymbolAddress((void**)&p_wouth, g_wouth);
    cudaGetSymbolAddress((void**)&p_kh,    g_kh);
    cudaGetSymbolAddress((void**)&p_vh,    g_vh);
    cudaGetSymbolAddress((void**)&p_atth,  g_atth);

    PFN_tmap_encode enc = get_encoder();

    CUtensorMap mX, mWqkv, mAtt, mWout, mK, mV;
    enc2d(enc, &mX,    p_xh,    CC, MM,   64, 128);
    enc2d(enc, &mWqkv, p_wqkvh, CC, NQKV, 64, 128);
    enc2d(enc, &mAtt,  p_atth,  CC, MM,   64, 128);
    enc2d(enc, &mWout, p_wouth, CC, CC,   64, 128);
    enc3d(enc, &mK, p_kh, DD, TT, BB * HH, 64, 64);
    enc3d(enc, &mV, p_vh, TT, DD, BB * HH, 64, 64);

    cudaFuncSetAttribute(gemm_qkv,
                         cudaFuncAttributeMaxDynamicSharedMemorySize, GEMM_SMEM);
    cudaFuncSetAttribute(gemm_out,
                         cudaFuncAttributeMaxDynamicSharedMemorySize, GEMM_SMEM);
    cudaFuncSetAttribute(attn_tma,
                         cudaFuncAttributeMaxDynamicSharedMemorySize, ATTN_SMEM);

    // 0) merged fp32 -> fp16 converts (one launch for x, w_qkv, w_out)
    cvt_all<<<NTOT / (8 * 256), 256>>>(x, w_qkv, w_out);

    // 1) qkv GEMM with fused RoPE + scatter (writes g_qh/g_kh/g_vh directly)
    {
        dim3 grid(NQKV / 128, MM / 128);
        gemm_qkv<<<grid, 256, GEMM_SMEM>>>(mX, mWqkv, cosp, sinp, NQKV, CC);
    }

    // 2) TMA fp16 causal flash attention
    {
        dim3 grid(TT / 128, BB * HH);
        attn_tma<<<grid, 256, ATTN_SMEM>>>(mK, mV, 0.125f * 1.44269504f);
    }

    // 3) out = att @ w_out^T (fp32 out)
    {
        dim3 grid(CC / 128, MM / 128);
        gemm_out<<<grid, 256, GEMM_SMEM>>>(mAtt, mWout, out, CC, CC);
    }
}

// round 17
// speedup vs baseline: 1.1242x; 1.0201x over previous
#include <cuda_runtime.h>
#include <cuda.h>
#include <cuda_fp16.h>
#include <cstdint>

// Problem constants
#define BB 2
#define TT 2048
#define HH 16
#define DD 64
#define CC 1024
#define MM (BB*TT)        // 4096 rows
#define NQKV (3*CC)       // 3072

// Scratch (device globals -- no allocation allowed)
__device__ __half g_xh[MM * CC];           // x in fp16
__device__ __half g_wqkvh[NQKV * CC];      // w_qkv in fp16
__device__ __half g_wouth[CC * CC];        // w_out in fp16
__device__ __half g_qh[BB*HH*TT*DD];       // [bh][t][d] fp16 (post-RoPE)
__device__ __half g_kh[BB*HH*TT*DD];       // [bh][t][d] fp16 (post-RoPE)
__device__ __half g_vh[BB*HH*DD*TT];       // [bh][d][t] fp16 (d-major)
__device__ __half g_atth[MM * CC];         // attention out, fp16 [B,T,C]

__device__ __forceinline__ float ex2(float x) {
    float y;
    asm("ex2.approx.ftz.f32 %0, %1;" : "=f"(y) : "f"(x));
    return y;
}

__device__ __forceinline__ void mma_f16(float* d, const uint32_t* a, const uint32_t* b) {
    asm volatile(
        "mma.sync.aligned.m16n8k16.row.col.f32.f16.f16.f32 "
        "{%0,%1,%2,%3},{%4,%5,%6,%7},{%8,%9},{%0,%1,%2,%3};\n"
        : "+f"(d[0]), "+f"(d[1]), "+f"(d[2]), "+f"(d[3])
        : "r"(a[0]), "r"(a[1]), "r"(a[2]), "r"(a[3]), "r"(b[0]), "r"(b[1]));
}

__device__ __forceinline__ void ldsm4(uint32_t* r, uint32_t addr) {
    asm volatile("ldmatrix.sync.aligned.m8n8.x4.shared.b16 {%0,%1,%2,%3}, [%4];"
                 : "=r"(r[0]), "=r"(r[1]), "=r"(r[2]), "=r"(r[3]) : "r"(addr));
}

__device__ __forceinline__ void fence_async() {
    asm volatile("fence.proxy.async.shared::cta;" ::: "memory");
}
__device__ __forceinline__ void mbar_init(uint32_t addr, uint32_t cnt) {
    asm volatile("mbarrier.init.shared.b64 [%0], %1;" :: "r"(addr), "r"(cnt) : "memory");
}
__device__ __forceinline__ void mbar_arrive(uint32_t addr) {
    asm volatile("mbarrier.arrive.release.cta.shared::cta.b64 _, [%0];"
                 :: "r"(addr) : "memory");
}
__device__ __forceinline__ void mbar_expect_tx(uint32_t addr, uint32_t bytes) {
    asm volatile("mbarrier.arrive.expect_tx.shared.b64 _, [%0], %1;"
                 :: "r"(addr), "r"(bytes) : "memory");
}
__device__ __forceinline__ void mbar_wait(uint32_t addr, uint32_t parity) {
    asm volatile(
        "{\n\t.reg .pred P;\n"
        "W:\n\tmbarrier.try_wait.parity.acquire.cta.shared::cta.b64 P, [%0], %1, 0x989680;\n"
        "\t@P bra D;\n\tbra W;\nD:\n\t}"
        :: "r"(addr), "r"(parity) : "memory");
}
__device__ __forceinline__ void tma2d(uint32_t smem, const CUtensorMap* map,
                                      int x, int y, uint32_t bar) {
    asm volatile(
        "cp.async.bulk.tensor.2d.shared::cta.global.tile.mbarrier::complete_tx::bytes "
        "[%0], [%1, {%2, %3}], [%4];"
        :: "r"(smem), "l"(map), "r"(x), "r"(y), "r"(bar) : "memory");
}
__device__ __forceinline__ void tma3d(uint32_t smem, const CUtensorMap* map,
                                      int x, int y, int z, uint32_t bar) {
    asm volatile(
        "cp.async.bulk.tensor.3d.shared::cta.global.tile.mbarrier::complete_tx::bytes "
        "[%0], [%1, {%2, %3, %4}], [%5];"
        :: "r"(smem), "l"(map), "r"(x), "r"(y), "r"(z), "r"(bar) : "memory");
}

// ---------------------------------------------------------------------------
// Merged fp32 -> fp16 convert for x, w_qkv, w_out in ONE launch.
// ---------------------------------------------------------------------------
#define N1 (MM*CC)          // 4194304
#define N2 (NQKV*CC)        // 3145728
#define N3 (CC*CC)          // 1048576
#define NTOT (N1+N2+N3)     // 8388608

__global__ __launch_bounds__(256) void cvt_all(
    const float* __restrict__ x,
    const float* __restrict__ wq,
    const float* __restrict__ wo)
{
    int i = (blockIdx.x * blockDim.x + threadIdx.x) * 8;
    if (i >= NTOT) return;
    const float* src;
    __half* dst;
    if (i < N1)            { src = x  + i;             dst = g_xh    + i; }
    else if (i < N1 + N2)  { src = wq + (i - N1);      dst = g_wqkvh + (i - N1); }
    else                   { src = wo + (i - N1 - N2); dst = g_wouth + (i - N1 - N2); }

    float4 v0 = *(const float4*)(src);
    float4 v1 = *(const float4*)(src + 4);
    __half2 h0 = __floats2half2_rn(v0.x, v0.y);
    __half2 h1 = __floats2half2_rn(v0.z, v0.w);
    __half2 h2 = __floats2half2_rn(v1.x, v1.y);
    __half2 h3 = __floats2half2_rn(v1.z, v1.w);
    uint4 o;
    o.x = *(uint32_t*)&h0; o.y = *(uint32_t*)&h1;
    o.z = *(uint32_t*)&h2; o.w = *(uint32_t*)&h3;
    *(uint4*)dst = o;
}

// ---------------------------------------------------------------------------
// Shared GEMM pipeline pieces
// smem: [0..24) full bars, [64..88) empty bars (count=8), tiles at 1024.
// ---------------------------------------------------------------------------
#define GS 3
#define GA_B 16384
#define GSTG (2*GA_B)                       // 32768 per stage (A+B)
#define GEMM_SMEM (1024 + GS*GSTG)          // 99328
#define CPITCH 136                          // halves; epilogue smem tile pitch

// ---------------------------------------------------------------------------
// qkv GEMM with fused RoPE + scatter epilogue; decoupled pipeline.
// ---------------------------------------------------------------------------
__global__ __launch_bounds__(256, 2) void gemm_qkv(
    const __grid_constant__ CUtensorMap mA,
    const __grid_constant__ CUtensorMap mB,
    const float* __restrict__ cosp, const float* __restrict__ sinp,
    int N, int K)
{
    extern __shared__ __align__(128) char smc[];
    uint32_t sb = (uint32_t)__cvta_generic_to_shared(smc);
    const uint32_t mb_full  = sb;
    const uint32_t mb_empty = sb + 64;
    const uint32_t tiles = sb + 1024;

    const int tid  = threadIdx.x;
    const int lane = tid & 31;
    const int warp = tid >> 5;
    const int wm = warp & 1;
    const int wn = warp >> 1;
    const int m0 = blockIdx.y * 128;
    const int n0 = blockIdx.x * 128;
    const int g  = lane >> 3;
    const int lr = lane & 7;
    const int gm = lane >> 2;
    const int gk = lane & 3;

    const int NI = K / 64;

    if (tid == 0) {
        #pragma unroll
        for (int s = 0; s < GS; s++) {
            mbar_init(mb_full + 8 * s, 1);
            mbar_init(mb_empty + 8 * s, 8);
        }
    }
    __syncthreads();

    auto prod = [&](int kt, int s) {
        uint32_t bar = mb_full + 8 * s;
        mbar_expect_tx(bar, GSTG);
        tma2d(tiles + s * GSTG,        &mA, kt * 64, m0, bar);
        tma2d(tiles + s * GSTG + GA_B, &mB, kt * 64, n0, bar);
    };
    if (tid == 0) { prod(0, 0); prod(1, 1); prod(2, 2); }

    uint32_t arow[4], brow[2];
    #pragma unroll
    for (int i = 0; i < 4; i++)
        arow[i] = (uint32_t)((wm * 64 + 16 * i + (g & 1) * 8 + lr) * 128);
    #pragma unroll
    for (int jj = 0; jj < 2; jj++)
        brow[jj] = (uint32_t)(GA_B + (wn * 32 + 16 * jj + (g >> 1) * 8 + lr) * 128);

    float acc[16][4];
    #pragma unroll
    for (int t = 0; t < 16; t++)
        #pragma unroll
        for (int r = 0; r < 4; r++) acc[t][r] = 0.f;

    for (int it = 0; it < NI; it++) {
        const int s = it % GS;
        const uint32_t ph = (uint32_t)((it / GS) & 1);
        mbar_wait(mb_full + 8 * s, ph);

        const uint32_t stg = tiles + s * GSTG;
        #pragma unroll
        for (int ks = 0; ks < 4; ks++) {
            uint32_t af[4][4];
            const uint32_t ag = (uint32_t)(((2 * ks + (g >> 1)) ^ lr) << 4);
            #pragma unroll
            for (int i = 0; i < 4; i++)
                ldsm4(af[i], stg + arow[i] + ag);
            uint32_t bf[2][4];
            const uint32_t bg = (uint32_t)(((2 * ks + (g & 1)) ^ lr) << 4);
            #pragma unroll
            for (int jj = 0; jj < 2; jj++)
                ldsm4(bf[jj], stg + brow[jj] + bg);

            #pragma unroll
            for (int i = 0; i < 4; i++)
                #pragma unroll
                for (int jj = 0; jj < 2; jj++) {
                    mma_f16(acc[i * 4 + 2 * jj],     af[i], &bf[jj][0]);
                    mma_f16(acc[i * 4 + 2 * jj + 1], af[i], &bf[jj][2]);
                }
        }
        fence_async();                          // generic reads -> async proxy
        if (lane == 0) mbar_arrive(mb_empty + 8 * s);
        if (tid == 0 && it + GS < NI) {
            mbar_wait(mb_empty + 8 * s, ph);
            prod(it + GS, s);
        }
    }

    // ---- fused epilogue: park C tile in smem (pipeline smem reused) ----
    __syncthreads();                        // all warps done with stage smem
    __half* cs = (__half*)(smc + 1024);
    #pragma unroll
    for (int i = 0; i < 4; i++) {
        #pragma unroll
        for (int nn = 0; nn < 4; nn++) {
            float* a = acc[i * 4 + nn];
            int r  = wm * 64 + 16 * i + gm;
            int cp = wn * 32 + 8 * nn + (gk << 1);
            __half2 v0 = __floats2half2_rn(a[0], a[1]);
            __half2 v1 = __floats2half2_rn(a[2], a[3]);
            *(uint32_t*)(cs + r * CPITCH + cp)       = *(uint32_t*)&v0;
            *(uint32_t*)(cs + (r + 8) * CPITCH + cp) = *(uint32_t*)&v1;
        }
    }
    __syncthreads();

    // ---- scatter: thread = one tile column x 64 rows ----
    const int colg  = tid & 127;
    const int rhalf = tid >> 7;
    const int c   = n0 + colg;
    const int reg = c >> 10;               // 0=q 1=k 2=v
    const int hd  = c & 1023;
    const int h   = hd >> 6, d = hd & 63;
    const int mb  = m0 + rhalf * 64;
    const int b   = mb >> 11;
    const int lr0 = rhalf * 64;

    if (reg < 2) {
        const int pcol = colg ^ 32;
        __half* dst = (reg == 0 ? g_qh : g_kh)
                      + ((size_t)(b * HH + h) * TT) * DD + d;
        const float sgn = (d < 32) ? -1.f : 1.f;
        for (int rr = 0; rr < 64; rr++) {
            int t = (mb + rr) & (TT - 1);
            float cv = cosp[t * DD + d];
            float sv = sinp[t * DD + d];
            float xm = __half2float(cs[(lr0 + rr) * CPITCH + colg]);
            float xp = __half2float(cs[(lr0 + rr) * CPITCH + pcol]);
            dst[(size_t)t * DD] = __float2half(xm * cv + sgn * xp * sv);
        }
    } else {
        __half* dst = g_vh + ((size_t)(b * HH + h) * DD + d) * TT;
        for (int rr = 0; rr < 64; rr += 8) {
            __half tmp[8];
            #pragma unroll
            for (int k = 0; k < 8; k++)
                tmp[k] = cs[(lr0 + rr + k) * CPITCH + colg];
            int t = (mb + rr) & (TT - 1);
            *(uint4*)(dst + t) = *(uint4*)tmp;
        }
    }
}

// ---------------------------------------------------------------------------
// Output-projection GEMM: C = A @ B^T, fp32 out; decoupled pipeline.
// ---------------------------------------------------------------------------
__global__ __launch_bounds__(256, 2) void gemm_out(
    const __grid_constant__ CUtensorMap mA,
    const __grid_constant__ CUtensorMap mB,
    float* __restrict__ C, int N, int K)
{
    extern __shared__ __align__(128) char smc[];
    uint32_t sb = (uint32_t)__cvta_generic_to_shared(smc);
    const uint32_t mb_full  = sb;
    const uint32_t mb_empty = sb + 64;
    const uint32_t tiles = sb + 1024;

    const int tid  = threadIdx.x;
    const int lane = tid & 31;
    const int warp = tid >> 5;
    const int wm = warp & 1;
    const int wn = warp >> 1;
    const int m0 = blockIdx.y * 128;
    const int n0 = blockIdx.x * 128;
    const int g  = lane >> 3;
    const int lr = lane & 7;
    const int gm = lane >> 2;
    const int gk = lane & 3;

    const int NI = K / 64;

    if (tid == 0) {
        #pragma unroll
        for (int s = 0; s < GS; s++) {
            mbar_init(mb_full + 8 * s, 1);
            mbar_init(mb_empty + 8 * s, 8);
        }
    }
    __syncthreads();

    auto prod = [&](int kt, int s) {
        uint32_t bar = mb_full + 8 * s;
        mbar_expect_tx(bar, GSTG);
        tma2d(tiles + s * GSTG,        &mA, kt * 64, m0, bar);
        tma2d(tiles + s * GSTG + GA_B, &mB, kt * 64, n0, bar);
    };
    if (tid == 0) { prod(0, 0); prod(1, 1); prod(2, 2); }

    uint32_t arow[4], brow[2];
    #pragma unroll
    for (int i = 0; i < 4; i++)
        arow[i] = (uint32_t)((wm * 64 + 16 * i + (g & 1) * 8 + lr) * 128);
    #pragma unroll
    for (int jj = 0; jj < 2; jj++)
        brow[jj] = (uint32_t)(GA_B + (wn * 32 + 16 * jj + (g >> 1) * 8 + lr) * 128);

    float acc[16][4];
    #pragma unroll
    for (int t = 0; t < 16; t++)
        #pragma unroll
        for (int r = 0; r < 4; r++) acc[t][r] = 0.f;

    for (int it = 0; it < NI; it++) {
        const int s = it % GS;
        const uint32_t ph = (uint32_t)((it / GS) & 1);
        mbar_wait(mb_full + 8 * s, ph);

        const uint32_t stg = tiles + s * GSTG;
        #pragma unroll
        for (int ks = 0; ks < 4; ks++) {
            uint32_t af[4][4];
            const uint32_t ag = (uint32_t)(((2 * ks + (g >> 1)) ^ lr) << 4);
            #pragma unroll
            for (int i = 0; i < 4; i++)
                ldsm4(af[i], stg + arow[i] + ag);
            uint32_t bf[2][4];
            const uint32_t bg = (uint32_t)(((2 * ks + (g & 1)) ^ lr) << 4);
            #pragma unroll
            for (int jj = 0; jj < 2; jj++)
                ldsm4(bf[jj], stg + brow[jj] + bg);

            #pragma unroll
            for (int i = 0; i < 4; i++)
                #pragma unroll
                for (int jj = 0; jj < 2; jj++) {
                    mma_f16(acc[i * 4 + 2 * jj],     af[i], &bf[jj][0]);
                    mma_f16(acc[i * 4 + 2 * jj + 1], af[i], &bf[jj][2]);
                }
        }
        fence_async();
        if (lane == 0) mbar_arrive(mb_empty + 8 * s);
        if (tid == 0 && it + GS < NI) {
            mbar_wait(mb_empty + 8 * s, ph);
            prod(it + GS, s);
        }
    }

    #pragma unroll
    for (int i = 0; i < 4; i++) {
        #pragma unroll
        for (int nn = 0; nn < 4; nn++) {
            float* a = acc[i * 4 + nn];
            int r = m0 + wm * 64 + 16 * i + gm;
            int c = n0 + wn * 32 + 8 * nn + (gk << 1);
            float2 v0 = {a[0], a[1]};
            float2 v1 = {a[2], a[3]};
            *(float2*)(C + (size_t)r * N + c) = v0;
            *(float2*)(C + (size_t)(r + 8) * N + c) = v1;
        }
    }
}

// ---------------------------------------------------------------------------
// TMA fp16 causal flash attention; decoupled pipeline + async fence.
// ---------------------------------------------------------------------------
#define AKT_B 8192
#define ASTG (2*AKT_B)                      // K+V = 16384
#define AST 3
#define ATTN_SMEM (1024 + AST*ASTG)         // 50176

__global__ __launch_bounds__(256, 2) void attn_tma(
    const __grid_constant__ CUtensorMap mK,
    const __grid_constant__ CUtensorMap mV,
    float kscale)
{
    const int bh = blockIdx.y;
    const int q0 = (gridDim.x - 1 - blockIdx.x) * 128;
    const int b = bh >> 4, h = bh & 15;
    const int tid = threadIdx.x;
    const int lane = tid & 31;
    const int w = tid >> 5;
    const int gm = lane >> 2;
    const int gk = lane & 3;
    const int g  = lane >> 3;
    const int lr = lane & 7;

    const __half* Qp = g_qh + (size_t)bh * TT * DD;

    extern __shared__ __align__(128) char smc[];
    uint32_t sb = (uint32_t)__cvta_generic_to_shared(smc);
    const uint32_t mb_full  = sb;
    const uint32_t mb_empty = sb + 64;

    const int rowA = q0 + w * 16 + gm;
    const int wrow_lo = q0 + w * 16;
    const int wrow_hi = wrow_lo + 15;

    const int ntiles = (q0 + 128) / 64;

    if (tid == 0) {
        #pragma unroll
        for (int s = 0; s < AST; s++) {
            mbar_init(mb_full + 8 * s, 1);
            mbar_init(mb_empty + 8 * s, 8);
        }
    }
    __syncthreads();

    const uint32_t tiles_u32 = sb + 1024;
    auto prod = [&](int jt, int s) {
        uint32_t bar = mb_full + 8 * s;
        mbar_expect_tx(bar, ASTG);
        tma3d(tiles_u32 + s * ASTG,         &mK, 0, jt * 64, bh, bar);
        tma3d(tiles_u32 + s * ASTG + AKT_B, &mV, jt * 64, 0, bh, bar);
    };
    if (tid == 0) {
        prod(0, 0);
        prod(1, 1);
        if (ntiles > 2) prod(2, 2);
    }

    uint32_t qf[4][4];
    #pragma unroll
    for (int s = 0; s < 4; s++) {
        const __half* r0 = Qp + (size_t)rowA * DD + 16 * s + 2 * gk;
        const __half* r1 = Qp + (size_t)(rowA + 8) * DD + 16 * s + 2 * gk;
        qf[s][0] = *(const uint32_t*)r0;
        qf[s][1] = *(const uint32_t*)r1;
        qf[s][2] = *(const uint32_t*)(r0 + 8);
        qf[s][3] = *(const uint32_t*)(r1 + 8);
    }

    const uint32_t lrowoff = (uint32_t)(((g >> 1) * 8 + lr) * 128);

    float o[8][4];
    #pragma unroll
    for (int n = 0; n < 8; n++)
        #pragma unroll
        for (int r = 0; r < 4; r++) o[n][r] = 0.f;
    float mA = -1e30f, mB = -1e30f, lA = 0.f, lB = 0.f;

    for (int jt = 0; jt < ntiles; jt++) {
        const int st = jt % AST;
        const uint32_t ph = (uint32_t)((jt / AST) & 1);
        mbar_wait(mb_full + 8 * st, ph);

        const uint32_t Ks = tiles_u32 + st * ASTG;
        const uint32_t Vs = Ks + AKT_B;
        const int j0 = jt * 64;

        if (j0 <= wrow_hi) {
            float sf[8][4];
            #pragma unroll
            for (int j = 0; j < 8; j++)
                #pragma unroll
                for (int r = 0; r < 4; r++) sf[j][r] = 0.f;
            #pragma unroll
            for (int s = 0; s < 4; s++) {
                const uint32_t bg = (uint32_t)(((2 * s + (g & 1)) ^ lr) << 4);
                #pragma unroll
                for (int jp = 0; jp < 4; jp++) {
                    uint32_t bf[4];
                    ldsm4(bf, Ks + (uint32_t)(16 * jp * 128) + lrowoff + bg);
                    mma_f16(sf[2 * jp],     qf[s], &bf[0]);
                    mma_f16(sf[2 * jp + 1], qf[s], &bf[2]);
                }
            }

            const bool needmask = (j0 + 63 > wrow_lo);
            float mxA = -1e30f, mxB = -1e30f;
            #pragma unroll
            for (int j = 0; j < 8; j++) {
                #pragma unroll
                for (int e = 0; e < 2; e++) {
                    int col = j0 + 8 * j + 2 * gk + e;
                    float v0 = sf[j][e] * kscale;
                    float v1 = sf[j][2 + e] * kscale;
                    if (needmask) {
                        if (col > rowA)     v0 = -1e30f;
                        if (col > rowA + 8) v1 = -1e30f;
                    }
                    sf[j][e] = v0; sf[j][2 + e] = v1;
                    mxA = fmaxf(mxA, v0); mxB = fmaxf(mxB, v1);
                }
            }
            mxA = fmaxf(mxA, __shfl_xor_sync(0xffffffffu, mxA, 1));
            mxA = fmaxf(mxA, __shfl_xor_sync(0xffffffffu, mxA, 2));
            mxB = fmaxf(mxB, __shfl_xor_sync(0xffffffffu, mxB, 1));
            mxB = fmaxf(mxB, __shfl_xor_sync(0xffffffffu, mxB, 2));

            float nmA = fmaxf(mA, mxA), nmB = fmaxf(mB, mxB);
            float aA = ex2(mA - nmA), aB = ex2(mB - nmB);
            mA = nmA; mB = nmB;

            #pragma unroll
            for (int n = 0; n < 8; n++) {
                o[n][0] *= aA; o[n][1] *= aA;
                o[n][2] *= aB; o[n][3] *= aB;
            }
            lA *= aA; lB *= aB;

            uint32_t phl[8][2];
            float slA = 0.f, slB = 0.f;
            #pragma unroll
            for (int j = 0; j < 8; j++) {
                float p0 = ex2(sf[j][0] - mA);
                float p1 = ex2(sf[j][1] - mA);
                float p2 = ex2(sf[j][2] - mB);
                float p3 = ex2(sf[j][3] - mB);
                slA += p0 + p1; slB += p2 + p3;
                __half2 h01 = __floats2half2_rn(p0, p1);
                __half2 h23 = __floats2half2_rn(p2, p3);
                phl[j][0] = *(const uint32_t*)&h01;
                phl[j][1] = *(const uint32_t*)&h23;
            }
            slA += __shfl_xor_sync(0xffffffffu, slA, 1);
            slA += __shfl_xor_sync(0xffffffffu, slA, 2);
            slB += __shfl_xor_sync(0xffffffffu, slB, 1);
            slB += __shfl_xor_sync(0xffffffffu, slB, 2);
            lA += slA; lB += slB;

            #pragma unroll
            for (int s2 = 0; s2 < 4; s2++) {
                uint32_t af[4] = { phl[2 * s2][0], phl[2 * s2][1],
                                   phl[2 * s2 + 1][0], phl[2 * s2 + 1][1] };
                const uint32_t vg = (uint32_t)(((2 * s2 + (g & 1)) ^ lr) << 4);
                #pragma unroll
                for (int jp = 0; jp < 4; jp++) {
                    uint32_t bf[4];
                    ldsm4(bf, Vs + (uint32_t)(16 * jp * 128) + lrowoff + vg);
                    mma_f16(o[2 * jp],     af, &bf[0]);
                    mma_f16(o[2 * jp + 1], af, &bf[2]);
                }
            }
        }
        fence_async();
        if (lane == 0) mbar_arrive(mb_empty + 8 * st);
        if (tid == 0 && jt + AST < ntiles) {
            mbar_wait(mb_empty + 8 * st, ph);
            prod(jt + AST, st);
        }
    }

    float invA = 1.f / lA, invB = 1.f / lB;
    __half* dstA = g_atth + (size_t)(b * TT + rowA) * CC + h * DD;
    __half* dstB = g_atth + (size_t)(b * TT + rowA + 8) * CC + h * DD;
    #pragma unroll
    for (int n = 0; n < 8; n++) {
        int cix = 8 * n + 2 * gk;
        __half2 v0 = __floats2half2_rn(o[n][0] * invA, o[n][1] * invA);
        __half2 v1 = __floats2half2_rn(o[n][2] * invB, o[n][3] * invB);
        *(uint32_t*)(dstA + cix) = *(uint32_t*)&v0;
        *(uint32_t*)(dstB + cix) = *(uint32_t*)&v1;
    }
}

// ---------------------------------------------------------------------------
// Host: tensor-map encode via driver entry point
// ---------------------------------------------------------------------------
typedef CUresult (*PFN_tmap_encode)(
    CUtensorMap*, CUtensorMapDataType, cuuint32_t, void*,
    const cuuint64_t*, const cuuint64_t*, const cuuint32_t*, const cuuint32_t*,
    CUtensorMapInterleave, CUtensorMapSwizzle, CUtensorMapL2promotion,
    CUtensorMapFloatOOBfill);

static PFN_tmap_encode get_encoder() {
    void* fn = nullptr;
    cudaDriverEntryPointQueryResult qr;
    cudaGetDriverEntryPoint("cuTensorMapEncodeTiled", &fn, cudaEnableDefault, &qr);
    return (PFN_tmap_encode)fn;
}

static void enc2d(PFN_tmap_encode f, CUtensorMap* m, void* base,
                  uint64_t d0, uint64_t d1, uint32_t b0, uint32_t b1) {
    cuuint64_t dims[2] = {d0, d1};
    cuuint64_t str[1]  = {d0 * 2};
    cuuint32_t box[2]  = {b0, b1};
    cuuint32_t es[2]   = {1, 1};
    f(m, CU_TENSOR_MAP_DATA_TYPE_FLOAT16, 2, base, dims, str, box, es,
      CU_TENSOR_MAP_INTERLEAVE_NONE, CU_TENSOR_MAP_SWIZZLE_128B,
      CU_TENSOR_MAP_L2_PROMOTION_L2_128B, CU_TENSOR_MAP_FLOAT_OOB_FILL_NONE);
}

static void enc3d(PFN_tmap_encode f, CUtensorMap* m, void* base,
                  uint64_t d0, uint64_t d1, uint64_t d2,
                  uint32_t b0, uint32_t b1) {
    cuuint64_t dims[3] = {d0, d1, d2};
    cuuint64_t str[2]  = {d0 * 2, d0 * d1 * 2};
    cuuint32_t box[3]  = {b0, b1, 1};
    cuuint32_t es[3]   = {1, 1, 1};
    f(m, CU_TENSOR_MAP_DATA_TYPE_FLOAT16, 3, base, dims, str, box, es,
      CU_TENSOR_MAP_INTERLEAVE_NONE, CU_TENSOR_MAP_SWIZZLE_128B,
      CU_TENSOR_MAP_L2_PROMOTION_L2_128B, CU_TENSOR_MAP_FLOAT_OOB_FILL_NONE);
}

// ---------------------------------------------------------------------------
// Launch
// ---------------------------------------------------------------------------
extern "C" void kernel_launch(void* const* d_in, const int* in_sizes, int n_in,
                              void* d_out, int out_size)
{
    const float* x     = (const float*)d_in[0];
    const float* cosp  = (const float*)d_in[1];
    const float* sinp  = (const float*)d_in[2];
    const float* w_qkv = (const float*)d_in[3];
    const float* w_out = (const float*)d_in[4];
    float* out = (float*)d_out;

    __half *p_xh, *p_wqkvh, *p_wouth, *p_kh, *p_vh, *p_atth;
    cudaGetSymbolAddress((void**)&p_xh,    g_xh);
    cudaGetSymbolAddress((void**)&p_wqkvh, g_wqkvh);
    cudaGetSymbolAddress((void**)&p_wouth, g_wouth);
    cudaGetSymbolAddress((void**)&p_kh,    g_kh);
    cudaGetSymbolAddress((void**)&p_vh,    g_vh);
    cudaGetSymbolAddress((void**)&p_atth,  g_atth);

    PFN_tmap_encode enc = get_encoder();

    CUtensorMap mX, mWqkv, mAtt, mWout, mK, mV;
    enc2d(enc, &mX,    p_xh,    CC, MM,   64, 128);
    enc2d(enc, &mWqkv, p_wqkvh, CC, NQKV, 64, 128);
    enc2d(enc, &mAtt,  p_atth,  CC, MM,   64, 128);
    enc2d(enc, &mWout, p_wouth, CC, CC,   64, 128);
    enc3d(enc, &mK, p_kh, DD, TT, BB * HH, 64, 64);
    enc3d(enc, &mV, p_vh, TT, DD, BB * HH, 64, 64);

    cudaFuncSetAttribute(gemm_qkv,
                         cudaFuncAttributeMaxDynamicSharedMemorySize, GEMM_SMEM);
    cudaFuncSetAttribute(gemm_out,
                         cudaFuncAttributeMaxDynamicSharedMemorySize, GEMM_SMEM);
    cudaFuncSetAttribute(attn_tma,
                         cudaFuncAttributeMaxDynamicSharedMemorySize, ATTN_SMEM);

    // 0) merged fp32 -> fp16 converts (one launch)
    cvt_all<<<NTOT / (8 * 256), 256>>>(x, w_qkv, w_out);

    // 1) qkv GEMM with fused RoPE + scatter
    {
        dim3 grid(NQKV / 128, MM / 128);
        gemm_qkv<<<grid, 256, GEMM_SMEM>>>(mX, mWqkv, cosp, sinp, NQKV, CC);
    }

    // 2) TMA fp16 causal flash attention
    {
        dim3 grid(TT / 128, BB * HH);
        attn_tma<<<grid, 256, ATTN_SMEM>>>(mK, mV, 0.125f * 1.44269504f);
    }

    // 3) out = att @ w_out^T (fp32 out)
    {
        dim3 grid(CC / 128, MM / 128);
        gemm_out<<<grid, 256, GEMM_SMEM>>>(mAtt, mWout, out, CC, CC);
    }
}